// round 1
// baseline (speedup 1.0000x reference)
#include <cuda_runtime.h>
#include <math.h>

#define B_    4
#define L_    16
#define NW_   64
#define D_    512
#define H_    8
#define HD_   64
#define NTOK_ 1024   // L_ * NW_
#define E3_   1536   // 3 * D_

// Scratch (allocation-free rule: __device__ globals)
__device__ float g_Q[B_ * H_ * NTOK_ * HD_];
__device__ float g_K[B_ * H_ * NTOK_ * HD_];
__device__ float g_V[B_ * H_ * NTOK_ * HD_];
__device__ float g_tqkv[B_ * L_ * 3 * HD_];

// ---------------------------------------------------------------------------
// Kernel 0: time qkv projection  tqkv[b,l,e] = te[b,l,:] . W_tqkv[e,:]
// grid = B_*L_ blocks, 192 threads (one per e)
// ---------------------------------------------------------------------------
__global__ void tqkv_kernel(const float* __restrict__ te,
                            const float* __restrict__ Wt) {
    __shared__ float s_te[D_];
    int bl = blockIdx.x;
    const float* row = te + bl * D_;
    for (int i = threadIdx.x; i < D_; i += blockDim.x) s_te[i] = row[i];
    __syncthreads();
    int e = threadIdx.x;  // 0..191
    const float4* w  = (const float4*)(Wt + e * D_);
    const float4* t4 = (const float4*)s_te;
    float acc = 0.f;
#pragma unroll 8
    for (int k = 0; k < D_ / 4; k++) {
        float4 a = t4[k], b = w[k];
        acc += a.x * b.x + a.y * b.y + a.z * b.z + a.w * b.w;
    }
    g_tqkv[bl * 192 + e] = acc;
}

// ---------------------------------------------------------------------------
// Kernel 1: QKV GEMM  [4096 x 512] @ [512 x 1536] with fused epilogue:
//   + time qkv add, head-split transpose to [b,h,N,hd], Q pre-scaled by 1/sqrt(d)
// tile: BM=64, BN=64, BK=16, 256 threads, 4x4 per thread
// ---------------------------------------------------------------------------
__global__ __launch_bounds__(256) void qkv_gemm(const float* __restrict__ x,
                                                const float* __restrict__ W) {
    __shared__ float As[16][68];
    __shared__ float Bs[16][68];
    int m0 = blockIdx.y * 64;
    int e0 = blockIdx.x * 64;
    int tid = threadIdx.x;
    int tx = tid & 15, ty = tid >> 4;
    int lrow = tid >> 2, lq = tid & 3;
    float acc[4][4] = {};

    for (int k0 = 0; k0 < D_; k0 += 16) {
        float4 av = *(const float4*)(x + (m0 + lrow) * D_ + k0 + lq * 4);
        float4 bv = *(const float4*)(W + (e0 + lrow) * D_ + k0 + lq * 4);
        As[lq * 4 + 0][lrow] = av.x; As[lq * 4 + 1][lrow] = av.y;
        As[lq * 4 + 2][lrow] = av.z; As[lq * 4 + 3][lrow] = av.w;
        Bs[lq * 4 + 0][lrow] = bv.x; Bs[lq * 4 + 1][lrow] = bv.y;
        Bs[lq * 4 + 2][lrow] = bv.z; Bs[lq * 4 + 3][lrow] = bv.w;
        __syncthreads();
#pragma unroll
        for (int kk = 0; kk < 16; kk++) {
            float4 a4 = *(const float4*)&As[kk][ty * 4];
            float4 b4 = *(const float4*)&Bs[kk][tx * 4];
            float a[4] = {a4.x, a4.y, a4.z, a4.w};
            float b[4] = {b4.x, b4.y, b4.z, b4.w};
#pragma unroll
            for (int i = 0; i < 4; i++)
#pragma unroll
                for (int j = 0; j < 4; j++) acc[i][j] += a[i] * b[j];
        }
        __syncthreads();
    }

    const float inv_scale = 0.044194173824159216f;  // 1/sqrt(512)
#pragma unroll
    for (int i = 0; i < 4; i++) {
        int m = m0 + ty * 4 + i;
        int b = m >> 10, l = (m >> 6) & 15, n = m & 63;
#pragma unroll
        for (int j = 0; j < 4; j++) {
            int e = e0 + tx * 4 + j;
            int third = e >> 9, wv = e & 511;
            int h = wv >> 6, hd = wv & 63;
            float val = acc[i][j] + g_tqkv[(b * 16 + l) * 192 + third * 64 + hd];
            float* dst = (third == 0) ? g_Q : ((third == 1) ? g_K : g_V);
            if (third == 0) val *= inv_scale;
            dst[((b * H_ + h) * NTOK_ + l * 64 + n) * HD_ + hd] = val;
        }
    }
}

// ---------------------------------------------------------------------------
// Kernel 2: fused attention, one block per (q-frame, head, batch).
// Streaming online-softmax over key-frames; masked frames skipped (exact:
// exp(BF16_MIN - max) == 0 in fp32). Relative bias = Qrow . emb_table[idx],
// constant within a key-frame.
// ---------------------------------------------------------------------------
struct AttnSmem {
    float Qs[64][68];
    float Ks[64][68];
    float Vs[64][68];
    float Ss[64][68];
    float Es[64];
    float bias[64];
    float mrow[64];
    float lrow[64];
    float crow[64];
};

extern __shared__ char smem_raw[];

__global__ __launch_bounds__(256) void attn_kernel(const int* __restrict__ pos,
                                                   const int* __restrict__ mask,
                                                   const float* __restrict__ emb,
                                                   float* __restrict__ out) {
    AttnSmem& s = *reinterpret_cast<AttnSmem*>(smem_raw);
    int ql = blockIdx.x, h = blockIdx.y, b = blockIdx.z;
    int tid = threadIdx.x;

    // Load Q frame (pre-scaled) to shared
    const float* Qg = g_Q + ((b * H_ + h) * NTOK_ + ql * 64) * HD_;
    for (int i = tid; i < 1024; i += 256) {
        int r = i >> 4, c = (i & 15) << 2;
        *(float4*)&s.Qs[r][c] = *(const float4*)(Qg + r * HD_ + c);
    }
    if (tid < 64) { s.mrow[tid] = -INFINITY; s.lrow[tid] = 0.f; }
    __syncthreads();

    // Phase-1 mapping: thread owns row qn1, kn subset (kn0 + 4*jj)
    int qn1 = tid >> 2, kn0 = tid & 3;
    float4 qreg[16];
#pragma unroll
    for (int c = 0; c < 16; c++) qreg[c] = *(const float4*)&s.Qs[qn1][c * 4];

    // Phase-3 mapping: thread owns row qn3, output dims [d0, d0+16)
    int qn3 = tid & 63, d0 = (tid >> 6) * 16;
    float4 O[4] = {{0,0,0,0},{0,0,0,0},{0,0,0,0},{0,0,0,0}};

    for (int kl = 0; kl < L_; kl++) {
        if (mask[(b * L_ + ql) * L_ + kl] == 0) continue;  // uniform branch

        const float* Kg = g_K + ((b * H_ + h) * NTOK_ + kl * 64) * HD_;
        const float* Vg = g_V + ((b * H_ + h) * NTOK_ + kl * 64) * HD_;
        for (int i = tid; i < 1024; i += 256) {
            int r = i >> 4, c = (i & 15) << 2;
            *(float4*)&s.Ks[r][c] = *(const float4*)(Kg + r * HD_ + c);
            *(float4*)&s.Vs[r][c] = *(const float4*)(Vg + r * HD_ + c);
        }
        int p = pos[(b * L_ + ql) * L_ + kl];
        p = min(max(p, -8), 8) + 8;
        if (tid < 64) s.Es[tid] = emb[p * HD_ + tid];
        __syncthreads();

        // Per-row relative bias (already scaled since Q is pre-scaled)
        if (tid < 64) {
            float acc = 0.f;
            const float* qrow = s.Qs[tid];
#pragma unroll 16
            for (int c = 0; c < 64; c++) acc += qrow[c] * s.Es[c];
            s.bias[tid] = acc;
        }
        __syncthreads();

        // Phase 1: 64x64 score tile
        float sc[16];
        float bq = s.bias[qn1];
#pragma unroll
        for (int jj = 0; jj < 16; jj++) sc[jj] = bq;
#pragma unroll
        for (int c = 0; c < 16; c++) {
            float4 qv = qreg[c];
#pragma unroll
            for (int jj = 0; jj < 16; jj++) {
                float4 kv = *(const float4*)&s.Ks[kn0 + jj * 4][c * 4];
                sc[jj] += qv.x * kv.x + qv.y * kv.y + qv.z * kv.z + qv.w * kv.w;
            }
        }
#pragma unroll
        for (int jj = 0; jj < 16; jj++) s.Ss[qn1][kn0 + jj * 4] = sc[jj];
        __syncthreads();

        // Phase 2: online softmax state per row
        if (tid < 64) {
            float* srow = s.Ss[tid];
            float rowmax = -INFINITY;
#pragma unroll 16
            for (int c = 0; c < 64; c++) rowmax = fmaxf(rowmax, srow[c]);
            float mold = s.mrow[tid];
            float mnew = fmaxf(mold, rowmax);
            float corr = __expf(mold - mnew);  // 0 on first processed frame
            float rsum = 0.f;
#pragma unroll 16
            for (int c = 0; c < 64; c++) {
                float pv = __expf(srow[c] - mnew);
                srow[c] = pv;
                rsum += pv;
            }
            s.lrow[tid] = s.lrow[tid] * corr + rsum;
            s.mrow[tid] = mnew;
            s.crow[tid] = corr;
        }
        __syncthreads();

        // Phase 3: O += P @ V with rescale
        float corr = s.crow[qn3];
#pragma unroll
        for (int u = 0; u < 4; u++) {
            O[u].x *= corr; O[u].y *= corr; O[u].z *= corr; O[u].w *= corr;
        }
#pragma unroll 8
        for (int kn = 0; kn < 64; kn++) {
            float pv = s.Ss[qn3][kn];
#pragma unroll
            for (int u = 0; u < 4; u++) {
                float4 vv = *(const float4*)&s.Vs[kn][d0 + u * 4];
                O[u].x += pv * vv.x; O[u].y += pv * vv.y;
                O[u].z += pv * vv.z; O[u].w += pv * vv.w;
            }
        }
        __syncthreads();  // protect Ks/Vs/Ss reuse next frame
    }

    // Finalize and store: out[b][ql][qn][h*64 + d0 .. ]
    float inv = 1.f / s.lrow[qn3];
    float* og = out + (size_t)((b * L_ + ql) * 64 + qn3) * D_ + h * HD_ + d0;
#pragma unroll
    for (int u = 0; u < 4; u++) {
        float4 v = O[u];
        v.x *= inv; v.y *= inv; v.z *= inv; v.w *= inv;
        *(float4*)(og + u * 4) = v;
    }
}

// ---------------------------------------------------------------------------
extern "C" void kernel_launch(void* const* d_in, const int* in_sizes, int n_in,
                              void* d_out, int out_size) {
    const float* x    = (const float*)d_in[0];
    const float* te   = (const float*)d_in[1];
    const int*   pos  = (const int*)d_in[2];
    const int*   mask = (const int*)d_in[3];
    const float* Wqkv = (const float*)d_in[4];
    const float* Wt   = (const float*)d_in[5];
    const float* emb  = (const float*)d_in[6];
    float* out = (float*)d_out;

    cudaFuncSetAttribute(attn_kernel, cudaFuncAttributeMaxDynamicSharedMemorySize,
                         (int)sizeof(AttnSmem));

    tqkv_kernel<<<B_ * L_, 192>>>(te, Wt);
    qkv_gemm<<<dim3(E3_ / 64, (B_ * NTOK_) / 64), 256>>>(x, Wqkv);
    attn_kernel<<<dim3(L_, H_, B_), 256, sizeof(AttnSmem)>>>(pos, mask, emb, out);
}

// round 2
// speedup vs baseline: 1.0531x; 1.0531x over previous
#include <cuda_runtime.h>
#include <math.h>

#define B_    4
#define L_    16
#define D_    512
#define H_    8
#define HD_   64
#define NTOK_ 1024   // L_ * NW
#define E3_   1536   // 3 * D_

// Scratch (allocation-free rule: __device__ globals)
__device__ float g_Q[B_ * H_ * NTOK_ * HD_];
__device__ float g_K[B_ * H_ * NTOK_ * HD_];
__device__ float g_V[B_ * H_ * NTOK_ * HD_];
__device__ float g_tqkv[B_ * L_ * 3 * HD_];

// ---------------------------------------------------------------------------
// Kernel 0: time qkv projection  tqkv[b,l,e] = te[b,l,:] . W_tqkv[e,:]
// grid = (64, 3), 256 threads; 4 threads per output, shfl reduction.
// ---------------------------------------------------------------------------
__global__ __launch_bounds__(256) void tqkv_kernel(const float* __restrict__ te,
                                                   const float* __restrict__ Wt) {
    __shared__ float s_te[D_];
    int bl = blockIdx.x;
    const float* row = te + bl * D_;
    for (int i = threadIdx.x; i < D_; i += 256) s_te[i] = row[i];
    __syncthreads();
    int el = threadIdx.x >> 2, q = threadIdx.x & 3;
    int e = blockIdx.y * 64 + el;
    const float4* w  = (const float4*)(Wt + e * D_) + q * 32;
    const float4* t4 = (const float4*)s_te + q * 32;
    float acc = 0.f;
#pragma unroll
    for (int k = 0; k < 32; k++) {
        float4 a = t4[k], b = w[k];
        acc += a.x * b.x + a.y * b.y + a.z * b.z + a.w * b.w;
    }
    acc += __shfl_xor_sync(0xffffffffu, acc, 1);
    acc += __shfl_xor_sync(0xffffffffu, acc, 2);
    if (q == 0) g_tqkv[bl * 192 + e] = acc;
}

// ---------------------------------------------------------------------------
// Kernel 1: QKV GEMM  [4096 x 512] @ [512 x 1536]^T layout (W is [e][k]),
// fused epilogue: time-qkv add, head-split transpose, Q pre-scale.
// BM=BN=128, BK=16, 256 threads, 8x8 per thread.
// Warp layout: 8 warps as 4(m) x 2(n); lanes as 4(m) x 8(n).
// ---------------------------------------------------------------------------
__global__ __launch_bounds__(256, 2) void qkv_gemm(const float* __restrict__ x,
                                                   const float* __restrict__ W) {
    __shared__ float As[16][132];
    __shared__ float Bs[16][132];
    int m0 = blockIdx.y * 128;
    int e0 = blockIdx.x * 128;
    int tid = threadIdx.x;
    int w = tid >> 5, lane = tid & 31;
    int wm = w & 3, wn = w >> 2;
    int lm = lane & 3, ln = lane >> 2;
    int mo = wm * 32 + lm * 8;   // microtile m offset in block tile
    int no = wn * 64 + ln * 8;   // microtile n offset

    int lr = tid >> 1;            // 0..127 : row within tile
    int lh = (tid & 1) * 8;       // k-offset: 0 or 8

    const float* xrow = x + (size_t)(m0 + lr) * D_ + lh;
    const float* wrow = W + (size_t)(e0 + lr) * D_ + lh;

    float acc[8][8] = {};

    for (int k0 = 0; k0 < D_; k0 += 16) {
        float4 a0 = *(const float4*)(xrow + k0);
        float4 a1 = *(const float4*)(xrow + k0 + 4);
        float4 b0 = *(const float4*)(wrow + k0);
        float4 b1 = *(const float4*)(wrow + k0 + 4);
        As[lh + 0][lr] = a0.x; As[lh + 1][lr] = a0.y; As[lh + 2][lr] = a0.z; As[lh + 3][lr] = a0.w;
        As[lh + 4][lr] = a1.x; As[lh + 5][lr] = a1.y; As[lh + 6][lr] = a1.z; As[lh + 7][lr] = a1.w;
        Bs[lh + 0][lr] = b0.x; Bs[lh + 1][lr] = b0.y; Bs[lh + 2][lr] = b0.z; Bs[lh + 3][lr] = b0.w;
        Bs[lh + 4][lr] = b1.x; Bs[lh + 5][lr] = b1.y; Bs[lh + 6][lr] = b1.z; Bs[lh + 7][lr] = b1.w;
        __syncthreads();
#pragma unroll
        for (int kk = 0; kk < 16; kk++) {
            float a[8], bb[8];
            *(float4*)&a[0]  = *(const float4*)&As[kk][mo];
            *(float4*)&a[4]  = *(const float4*)&As[kk][mo + 4];
            *(float4*)&bb[0] = *(const float4*)&Bs[kk][no];
            *(float4*)&bb[4] = *(const float4*)&Bs[kk][no + 4];
#pragma unroll
            for (int i = 0; i < 8; i++)
#pragma unroll
                for (int j = 0; j < 8; j++) acc[i][j] += a[i] * bb[j];
        }
        __syncthreads();
    }

    const float inv_scale = 0.044194173824159216f;  // 1/sqrt(512)
#pragma unroll
    for (int i = 0; i < 8; i++) {
        int m = m0 + mo + i;
        int b = m >> 10, l = (m >> 6) & 15, n = m & 63;
        const float* tq = g_tqkv + (b * 16 + l) * 192;
#pragma unroll
        for (int j = 0; j < 8; j++) {
            int e = e0 + no + j;
            int third = e >> 9, wv = e & 511;
            int h = wv >> 6, hd = wv & 63;
            float val = acc[i][j] + tq[third * 64 + hd];
            float* dst = (third == 0) ? g_Q : ((third == 1) ? g_K : g_V);
            if (third == 0) val *= inv_scale;
            dst[((b * H_ + h) * NTOK_ + l * 64 + n) * HD_ + hd] = val;
        }
    }
}

// ---------------------------------------------------------------------------
// Kernel 2: fused attention, one block per (q-frame, head, batch).
// - All 16 frame biases precomputed once (256 threads).
// - Softmax fused into QK phase: each score row owned by 4 consecutive lanes
//   of one warp; shfl reductions; online-softmax state in shared.
// - Masked key-frames skipped entirely (exact: exp underflow -> 0).
// ---------------------------------------------------------------------------
struct AttnSmem {
    float Qs[64][68];
    float Ks[64][68];
    float Vs[64][68];
    float Ss[64][68];
    float Et[16][65];     // emb rows per key frame (padded: stride 65)
    float biasS[64][17];  // per (q-row, key-frame) relative bias
    float mS[64];
    float lS[64];
    float cS[64];
};

extern __shared__ char smem_raw[];

__global__ __launch_bounds__(256) void attn_kernel(const int* __restrict__ pos,
                                                   const int* __restrict__ mask,
                                                   const float* __restrict__ emb,
                                                   float* __restrict__ out) {
    AttnSmem& s = *reinterpret_cast<AttnSmem*>(smem_raw);
    int ql = blockIdx.x, h = blockIdx.y, b = blockIdx.z;
    int tid = threadIdx.x;

    // Load Q frame (pre-scaled by 1/sqrt(d))
    const float* Qg = g_Q + ((b * H_ + h) * NTOK_ + ql * 64) * HD_;
    for (int i = tid; i < 1024; i += 256) {
        int r = i >> 4, c = (i & 15) << 2;
        *(float4*)&s.Qs[r][c] = *(const float4*)(Qg + r * HD_ + c);
    }
    // Load embedding rows for all 16 key frames
    for (int i = tid; i < 1024; i += 256) {
        int kl = i >> 6, c = i & 63;
        int p = pos[(b * L_ + ql) * L_ + kl];
        p = min(max(p, -8), 8) + 8;
        s.Et[kl][c] = emb[p * HD_ + c];
    }
    if (tid < 64) { s.mS[tid] = -INFINITY; s.lS[tid] = 0.f; }
    __syncthreads();

    // Precompute bias[r][kl] = Qrow(r) . Et[kl]  (1024 dot-64s, 4 per thread)
#pragma unroll
    for (int u = 0; u < 4; u++) {
        int id = tid + u * 256;
        int r = id >> 4, kl = id & 15;
        float acc = 0.f;
        const float* qrow = s.Qs[r];
        const float* erow = s.Et[kl];
#pragma unroll 16
        for (int c = 0; c < 64; c++) acc += qrow[c] * erow[c];
        s.biasS[r][kl] = acc;
    }

    // Phase-1 mapping: row qn1 = tid>>2 owned by 4 consecutive lanes (kn0)
    int qn1 = tid >> 2, kn0 = tid & 3;
    // Phase-3 mapping: row qn3, output dims [d0, d0+16)
    int qn3 = tid & 63, d0 = (tid >> 6) * 16;

    __syncthreads();

    float4 qreg[16];
#pragma unroll
    for (int c = 0; c < 16; c++) qreg[c] = *(const float4*)&s.Qs[qn1][c * 4];

    float4 O[4] = {{0,0,0,0},{0,0,0,0},{0,0,0,0},{0,0,0,0}};

    for (int kl = 0; kl < L_; kl++) {
        if (mask[(b * L_ + ql) * L_ + kl] == 0) continue;  // uniform branch

        const float* Kg = g_K + ((b * H_ + h) * NTOK_ + kl * 64) * HD_;
        const float* Vg = g_V + ((b * H_ + h) * NTOK_ + kl * 64) * HD_;
        for (int i = tid; i < 1024; i += 256) {
            int r = i >> 4, c = (i & 15) << 2;
            *(float4*)&s.Ks[r][c] = *(const float4*)(Kg + r * HD_ + c);
            *(float4*)&s.Vs[r][c] = *(const float4*)(Vg + r * HD_ + c);
        }
        __syncthreads();

        // Phase 1: scores for row qn1, cols kn0 + 4*jj  (bias pre-added)
        float sc[16];
        float bq = s.biasS[qn1][kl];
#pragma unroll
        for (int jj = 0; jj < 16; jj++) sc[jj] = bq;
#pragma unroll
        for (int c = 0; c < 16; c++) {
            float4 qv = qreg[c];
#pragma unroll
            for (int jj = 0; jj < 16; jj++) {
                float4 kv = *(const float4*)&s.Ks[kn0 + jj * 4][c * 4];
                sc[jj] += qv.x * kv.x + qv.y * kv.y + qv.z * kv.z + qv.w * kv.w;
            }
        }

        // In-warp online softmax over the 4-lane row group
        float mx = sc[0];
#pragma unroll
        for (int jj = 1; jj < 16; jj++) mx = fmaxf(mx, sc[jj]);
        mx = fmaxf(mx, __shfl_xor_sync(0xffffffffu, mx, 1));
        mx = fmaxf(mx, __shfl_xor_sync(0xffffffffu, mx, 2));
        float mold = s.mS[qn1];
        float mnew = fmaxf(mold, mx);
        float rsum = 0.f;
#pragma unroll
        for (int jj = 0; jj < 16; jj++) {
            float pv = __expf(sc[jj] - mnew);
            sc[jj] = pv;
            rsum += pv;
        }
        rsum += __shfl_xor_sync(0xffffffffu, rsum, 1);
        rsum += __shfl_xor_sync(0xffffffffu, rsum, 2);
#pragma unroll
        for (int jj = 0; jj < 16; jj++) s.Ss[qn1][kn0 + jj * 4] = sc[jj];
        if (kn0 == 0) {
            float corr = __expf(mold - mnew);  // 0 on first processed frame
            s.cS[qn1] = corr;
            s.mS[qn1] = mnew;
            s.lS[qn1] = s.lS[qn1] * corr + rsum;
        }
        __syncthreads();

        // Phase 3: O = O*corr + P @ V  (float4 P reads: conflict-free-ish)
        float corr = s.cS[qn3];
#pragma unroll
        for (int u = 0; u < 4; u++) {
            O[u].x *= corr; O[u].y *= corr; O[u].z *= corr; O[u].w *= corr;
        }
#pragma unroll 4
        for (int k4 = 0; k4 < 16; k4++) {
            float4 p4 = *(const float4*)&s.Ss[qn3][k4 * 4];
            float pe[4] = {p4.x, p4.y, p4.z, p4.w};
#pragma unroll
            for (int e = 0; e < 4; e++) {
                float pv = pe[e];
                int kn = k4 * 4 + e;
#pragma unroll
                for (int u = 0; u < 4; u++) {
                    float4 vv = *(const float4*)&s.Vs[kn][d0 + u * 4];
                    O[u].x += pv * vv.x; O[u].y += pv * vv.y;
                    O[u].z += pv * vv.z; O[u].w += pv * vv.w;
                }
            }
        }
        __syncthreads();  // protect Ks/Vs/Ss reuse next frame
    }

    // Finalize: out[b][ql][qn][h*64 + d0..]
    float inv = 1.f / s.lS[qn3];
    float* og = out + (size_t)((b * L_ + ql) * 64 + qn3) * D_ + h * HD_ + d0;
#pragma unroll
    for (int u = 0; u < 4; u++) {
        float4 v = O[u];
        v.x *= inv; v.y *= inv; v.z *= inv; v.w *= inv;
        *(float4*)(og + u * 4) = v;
    }
}

// ---------------------------------------------------------------------------
extern "C" void kernel_launch(void* const* d_in, const int* in_sizes, int n_in,
                              void* d_out, int out_size) {
    const float* x    = (const float*)d_in[0];
    const float* te   = (const float*)d_in[1];
    const int*   pos  = (const int*)d_in[2];
    const int*   mask = (const int*)d_in[3];
    const float* Wqkv = (const float*)d_in[4];
    const float* Wt   = (const float*)d_in[5];
    const float* emb  = (const float*)d_in[6];
    float* out = (float*)d_out;

    cudaFuncSetAttribute(attn_kernel, cudaFuncAttributeMaxDynamicSharedMemorySize,
                         (int)sizeof(AttnSmem));

    tqkv_kernel<<<dim3(B_ * L_, 3), 256>>>(te, Wt);
    qkv_gemm<<<dim3(E3_ / 128, (B_ * NTOK_) / 128), 256>>>(x, Wqkv);
    attn_kernel<<<dim3(L_, H_, B_), 256, sizeof(AttnSmem)>>>(pos, mask, emb, out);
}

// round 4
// speedup vs baseline: 1.2720x; 1.2078x over previous
#include <cuda_runtime.h>
#include <cuda_bf16.h>
#include <math.h>
#include <stdint.h>

#define B_    4
#define L_    16
#define D_    512
#define H_    8
#define HD_   64
#define NTOK_ 1024
#define E3_   1536

// Scratch (allocation-free rule: __device__ globals)
__device__ float g_Q[B_ * H_ * NTOK_ * HD_];
__device__ float g_K[B_ * H_ * NTOK_ * HD_];
__device__ float g_V[B_ * H_ * NTOK_ * HD_];
__device__ __nv_bfloat16 g_Xhi[4096 * 512];
__device__ __nv_bfloat16 g_Xlo[4096 * 512];
__device__ __nv_bfloat16 g_Whi[1536 * 512];
__device__ __nv_bfloat16 g_Wlo[1536 * 512];

__device__ __forceinline__ uint32_t smem_u32(const void* p) {
    uint32_t a;
    asm("{ .reg .u64 t; cvta.to.shared.u64 t, %1; cvt.u32.u64 %0, t; }" : "=r"(a) : "l"(p));
    return a;
}
__device__ __forceinline__ void ldsm4(uint32_t* r, uint32_t addr) {
    asm volatile("ldmatrix.sync.aligned.m8n8.x4.shared.b16 {%0,%1,%2,%3}, [%4];"
        : "=r"(r[0]), "=r"(r[1]), "=r"(r[2]), "=r"(r[3]) : "r"(addr));
}
__device__ __forceinline__ void mma16816(float* c, const uint32_t* a, uint32_t b0, uint32_t b1) {
    asm volatile("mma.sync.aligned.m16n8k16.row.col.f32.bf16.bf16.f32 "
        "{%0,%1,%2,%3}, {%4,%5,%6,%7}, {%8,%9}, {%0,%1,%2,%3};"
        : "+f"(c[0]), "+f"(c[1]), "+f"(c[2]), "+f"(c[3])
        : "r"(a[0]), "r"(a[1]), "r"(a[2]), "r"(a[3]), "r"(b0), "r"(b1));
}

// ---------------------------------------------------------------------------
// Kernel 0: split X and W into bf16 (hi, lo) pairs.
// ---------------------------------------------------------------------------
#define XQUADS 524288   // 4096*512/4
#define WQUADS 196608   // 1536*512/4

__global__ __launch_bounds__(256) void split_kernel(const float* __restrict__ x,
                                                    const float* __restrict__ W) {
    int i = blockIdx.x * 256 + threadIdx.x;
    const float4* src;
    __nv_bfloat16 *hi, *lo;
    int idx;
    if (i < XQUADS) { src = (const float4*)x; hi = g_Xhi; lo = g_Xlo; idx = i; }
    else            { src = (const float4*)W; hi = g_Whi; lo = g_Wlo; idx = i - XQUADS; }
    float4 v = src[idx];
    float f[4] = {v.x, v.y, v.z, v.w};
    __nv_bfloat162* hp = (__nv_bfloat162*)hi;
    __nv_bfloat162* lp = (__nv_bfloat162*)lo;
#pragma unroll
    for (int j = 0; j < 2; j++) {
        __nv_bfloat16 h0 = __float2bfloat16_rn(f[2 * j]);
        __nv_bfloat16 h1 = __float2bfloat16_rn(f[2 * j + 1]);
        __nv_bfloat16 l0 = __float2bfloat16_rn(f[2 * j] - __bfloat162float(h0));
        __nv_bfloat16 l1 = __float2bfloat16_rn(f[2 * j + 1] - __bfloat162float(h1));
        hp[idx * 2 + j] = __halves2bfloat162(h0, h1);
        lp[idx * 2 + j] = __halves2bfloat162(l0, l1);
    }
}

// ---------------------------------------------------------------------------
// Kernel 1: QKV GEMM via bf16 mma.sync, K' = 1536 (3x split trick).
// C[4096,1536] = [Xhi|Xlo|Xhi] . [Whi|Whi|Wlo]^T
// BM=BN=128, BK=32(bf16), 256 threads, warp grid 2m x 4n, warp tile 64x32.
// Epilogue: + in-block tqkv, head-split scatter, Q pre-scale.
// ---------------------------------------------------------------------------
__global__ __launch_bounds__(256, 2) void qkv_gemm(const float* __restrict__ te,
                                                   const float* __restrict__ Wt) {
    __shared__ __align__(16) uint8_t sAbuf[2][128 * 64];
    __shared__ __align__(16) uint8_t sBbuf[2][128 * 64];
    __shared__ float s_tq[128];

    int tid = threadIdx.x;
    int m0 = blockIdx.y * 128, e0 = blockIdx.x * 128;
    int bb = m0 >> 10, l0 = (m0 >> 6) & 15, third = e0 >> 9;

    // in-block tqkv: s_tq[fr*64+hd] = te[bb, l0+fr, :] . Wt[third*64+hd, :]
    {
        int outi = tid >> 1, half = tid & 1;
        int fr = outi >> 6, hd = outi & 63;
        const float4* tp = (const float4*)(te + (size_t)(bb * 16 + l0 + fr) * D_) + half * 64;
        const float4* wp = (const float4*)(Wt + (size_t)(third * 64 + hd) * D_) + half * 64;
        float acc = 0.f;
#pragma unroll 8
        for (int k = 0; k < 64; k++) {
            float4 a = tp[k], w = wp[k];
            acc += a.x * w.x + a.y * w.y + a.z * w.z + a.w * w.w;
        }
        acc += __shfl_xor_sync(0xffffffffu, acc, 1);
        if (!half) s_tq[outi] = acc;
    }

    uint32_t aBase = smem_u32(sAbuf), bBase = smem_u32(sBbuf);

    // cp.async mapping: thread -> row tid>>1, two 16B chunks
    int mld = tid >> 1;
    int kc0 = (tid & 1) * 2;
    int swm = (mld >> 1) & 3;
    uint32_t dA0 = aBase + mld * 64, dB0 = bBase + mld * 64;
    const __nv_bfloat16* Asrc = g_Xhi + (size_t)(m0 + mld) * 512;
    const __nv_bfloat16* Alo  = g_Xlo + (size_t)(m0 + mld) * 512;
    const __nv_bfloat16* Bsrc = g_Whi + (size_t)(e0 + mld) * 512;
    const __nv_bfloat16* Blo  = g_Wlo + (size_t)(e0 + mld) * 512;

    // fragment lane addressing
    int lane = tid & 31, warp = tid >> 5;
    int wm = warp & 1, wn = warp >> 1;
    uint32_t aAddr[4]; int aXor[4];
    int rA = lane & 15, kcbA = lane >> 4;
    {
#pragma unroll
        for (int im = 0; im < 4; im++) {
            int mr = wm * 64 + im * 16 + rA;
            aAddr[im] = aBase + mr * 64;
            aXor[im] = (mr >> 1) & 3;
        }
    }
    uint32_t bAddr[2]; int bXor[2];
    int kcbB = (lane >> 3) & 1;
    {
#pragma unroll
        for (int p = 0; p < 2; p++) {
            int nr = wn * 32 + p * 16 + (lane & 7) + ((lane >> 4) << 3);
            bAddr[p] = bBase + nr * 64;
            bXor[p] = (nr >> 1) & 3;
        }
    }

    float c[4][4][4] = {};

#define ISSUE(ki) do {                                                          \
    int _r = (ki) >> 4, _kb = ((ki) & 15) * 32, _st = (ki) & 1;                 \
    const __nv_bfloat16* _ap = (_r == 1) ? Alo : Asrc;                          \
    const __nv_bfloat16* _bp = (_r == 2) ? Blo : Bsrc;                          \
    _Pragma("unroll")                                                           \
    for (int _j = 0; _j < 2; _j++) {                                            \
        int _kc = kc0 + _j;                                                     \
        const void* _sa = _ap + _kb + _kc * 8;                                  \
        const void* _sb = _bp + _kb + _kc * 8;                                  \
        uint32_t _da = dA0 + _st * 8192 + (((_kc) ^ swm) << 4);                 \
        uint32_t _db = dB0 + _st * 8192 + (((_kc) ^ swm) << 4);                 \
        asm volatile("cp.async.cg.shared.global [%0], [%1], 16;" :: "r"(_da), "l"(_sa)); \
        asm volatile("cp.async.cg.shared.global [%0], [%1], 16;" :: "r"(_db), "l"(_sb)); \
    }                                                                           \
    asm volatile("cp.async.commit_group;");                                     \
} while (0)

    ISSUE(0);
    for (int ki = 0; ki < 48; ki++) {
        if (ki + 1 < 48) {
            ISSUE(ki + 1);
            asm volatile("cp.async.wait_group 1;" ::: "memory");
        } else {
            asm volatile("cp.async.wait_group 0;" ::: "memory");
        }
        __syncthreads();
        int st = ki & 1;
#pragma unroll
        for (int s = 0; s < 2; s++) {
            uint32_t a[4][4];
#pragma unroll
            for (int im = 0; im < 4; im++)
                ldsm4(a[im], aAddr[im] + st * 8192 + (((kcbA + 2 * s) ^ aXor[im]) << 4));
            uint32_t bq[2][4];
#pragma unroll
            for (int p = 0; p < 2; p++)
                ldsm4(bq[p], bAddr[p] + st * 8192 + (((kcbB + 2 * s) ^ bXor[p]) << 4));
#pragma unroll
            for (int im = 0; im < 4; im++)
#pragma unroll
                for (int in = 0; in < 4; in++)
                    mma16816(c[im][in], a[im], bq[in >> 1][(in & 1) * 2], bq[in >> 1][(in & 1) * 2 + 1]);
        }
        __syncthreads();
    }

    // epilogue
    const float inv_scale = 0.044194173824159216f;  // 1/sqrt(512)
    int gid = lane >> 2, tig = lane & 3;
    float* dst = (third == 0) ? g_Q : ((third == 1) ? g_K : g_V);
#pragma unroll
    for (int im = 0; im < 4; im++) {
#pragma unroll
        for (int hrow = 0; hrow < 2; hrow++) {
            int row = m0 + wm * 64 + im * 16 + gid + hrow * 8;
            int b = row >> 10, l = (row >> 6) & 15, nt = row & 63;
            int frl = (row >> 6) & 1;
#pragma unroll
            for (int in = 0; in < 4; in++) {
                int e = e0 + wn * 32 + in * 8 + 2 * tig;
                int h = (e >> 6) & 7, hd = e & 63;
                float v0 = c[im][in][2 * hrow + 0] + s_tq[frl * 64 + hd];
                float v1 = c[im][in][2 * hrow + 1] + s_tq[frl * 64 + hd + 1];
                if (third == 0) { v0 *= inv_scale; v1 *= inv_scale; }
                float2 vv = make_float2(v0, v1);
                *(float2*)(dst + (size_t)((b * H_ + h) * NTOK_ + l * 64 + nt) * HD_ + hd) = vv;
            }
        }
    }
}

// ---------------------------------------------------------------------------
// Kernel 2: fused attention (round-2 known-good version, fp32)
// ---------------------------------------------------------------------------
struct AttnSmem {
    float Qs[64][68];
    float Ks[64][68];
    float Vs[64][68];
    float Ss[64][68];
    float Et[16][65];
    float biasS[64][17];
    float mS[64];
    float lS[64];
    float cS[64];
};

extern __shared__ char smem_raw[];

__global__ __launch_bounds__(256) void attn_kernel(const int* __restrict__ pos,
                                                   const int* __restrict__ mask,
                                                   const float* __restrict__ emb,
                                                   float* __restrict__ out) {
    AttnSmem& s = *reinterpret_cast<AttnSmem*>(smem_raw);
    int ql = blockIdx.x, h = blockIdx.y, b = blockIdx.z;
    int tid = threadIdx.x;

    const float* Qg = g_Q + ((b * H_ + h) * NTOK_ + ql * 64) * HD_;
    for (int i = tid; i < 1024; i += 256) {
        int r = i >> 4, c = (i & 15) << 2;
        *(float4*)&s.Qs[r][c] = *(const float4*)(Qg + r * HD_ + c);
    }
    for (int i = tid; i < 1024; i += 256) {
        int kl = i >> 6, c = i & 63;
        int p = pos[(b * L_ + ql) * L_ + kl];
        p = min(max(p, -8), 8) + 8;
        s.Et[kl][c] = emb[p * HD_ + c];
    }
    if (tid < 64) { s.mS[tid] = -INFINITY; s.lS[tid] = 0.f; }
    __syncthreads();

#pragma unroll
    for (int u = 0; u < 4; u++) {
        int id = tid + u * 256;
        int r = id >> 4, kl = id & 15;
        float acc = 0.f;
        const float* qrow = s.Qs[r];
        const float* erow = s.Et[kl];
#pragma unroll 16
        for (int c = 0; c < 64; c++) acc += qrow[c] * erow[c];
        s.biasS[r][kl] = acc;
    }

    int qn1 = tid >> 2, kn0 = tid & 3;
    int qn3 = tid & 63, d0 = (tid >> 6) * 16;

    __syncthreads();

    float4 qreg[16];
#pragma unroll
    for (int c = 0; c < 16; c++) qreg[c] = *(const float4*)&s.Qs[qn1][c * 4];

    float4 O[4] = {{0,0,0,0},{0,0,0,0},{0,0,0,0},{0,0,0,0}};

    for (int kl = 0; kl < L_; kl++) {
        if (mask[(b * L_ + ql) * L_ + kl] == 0) continue;

        const float* Kg = g_K + ((b * H_ + h) * NTOK_ + kl * 64) * HD_;
        const float* Vg = g_V + ((b * H_ + h) * NTOK_ + kl * 64) * HD_;
        for (int i = tid; i < 1024; i += 256) {
            int r = i >> 4, c = (i & 15) << 2;
            *(float4*)&s.Ks[r][c] = *(const float4*)(Kg + r * HD_ + c);
            *(float4*)&s.Vs[r][c] = *(const float4*)(Vg + r * HD_ + c);
        }
        __syncthreads();

        float sc[16];
        float bq = s.biasS[qn1][kl];
#pragma unroll
        for (int jj = 0; jj < 16; jj++) sc[jj] = bq;
#pragma unroll
        for (int c = 0; c < 16; c++) {
            float4 qv = qreg[c];
#pragma unroll
            for (int jj = 0; jj < 16; jj++) {
                float4 kv = *(const float4*)&s.Ks[kn0 + jj * 4][c * 4];
                sc[jj] += qv.x * kv.x + qv.y * kv.y + qv.z * kv.z + qv.w * kv.w;
            }
        }

        float mx = sc[0];
#pragma unroll
        for (int jj = 1; jj < 16; jj++) mx = fmaxf(mx, sc[jj]);
        mx = fmaxf(mx, __shfl_xor_sync(0xffffffffu, mx, 1));
        mx = fmaxf(mx, __shfl_xor_sync(0xffffffffu, mx, 2));
        float mold = s.mS[qn1];
        float mnew = fmaxf(mold, mx);
        float rsum = 0.f;
#pragma unroll
        for (int jj = 0; jj < 16; jj++) {
            float pv = __expf(sc[jj] - mnew);
            sc[jj] = pv;
            rsum += pv;
        }
        rsum += __shfl_xor_sync(0xffffffffu, rsum, 1);
        rsum += __shfl_xor_sync(0xffffffffu, rsum, 2);
#pragma unroll
        for (int jj = 0; jj < 16; jj++) s.Ss[qn1][kn0 + jj * 4] = sc[jj];
        if (kn0 == 0) {
            float corr = __expf(mold - mnew);
            s.cS[qn1] = corr;
            s.mS[qn1] = mnew;
            s.lS[qn1] = s.lS[qn1] * corr + rsum;
        }
        __syncthreads();

        float corr = s.cS[qn3];
#pragma unroll
        for (int u = 0; u < 4; u++) {
            O[u].x *= corr; O[u].y *= corr; O[u].z *= corr; O[u].w *= corr;
        }
#pragma unroll 4
        for (int k4 = 0; k4 < 16; k4++) {
            float4 p4 = *(const float4*)&s.Ss[qn3][k4 * 4];
            float pe[4] = {p4.x, p4.y, p4.z, p4.w};
#pragma unroll
            for (int e = 0; e < 4; e++) {
                float pv = pe[e];
                int kn = k4 * 4 + e;
#pragma unroll
                for (int u = 0; u < 4; u++) {
                    float4 vv = *(const float4*)&s.Vs[kn][d0 + u * 4];
                    O[u].x += pv * vv.x; O[u].y += pv * vv.y;
                    O[u].z += pv * vv.z; O[u].w += pv * vv.w;
                }
            }
        }
        __syncthreads();
    }

    float inv = 1.f / s.lS[qn3];
    float* og = out + (size_t)((b * L_ + ql) * 64 + qn3) * D_ + h * HD_ + d0;
#pragma unroll
    for (int u = 0; u < 4; u++) {
        float4 v = O[u];
        v.x *= inv; v.y *= inv; v.z *= inv; v.w *= inv;
        *(float4*)(og + u * 4) = v;
    }
}

// ---------------------------------------------------------------------------
extern "C" void kernel_launch(void* const* d_in, const int* in_sizes, int n_in,
                              void* d_out, int out_size) {
    const float* x    = (const float*)d_in[0];
    const float* te   = (const float*)d_in[1];
    const int*   pos  = (const int*)d_in[2];
    const int*   mask = (const int*)d_in[3];
    const float* Wqkv = (const float*)d_in[4];
    const float* Wt   = (const float*)d_in[5];
    const float* emb  = (const float*)d_in[6];
    float* out = (float*)d_out;

    cudaFuncSetAttribute(attn_kernel, cudaFuncAttributeMaxDynamicSharedMemorySize,
                         (int)sizeof(AttnSmem));

    split_kernel<<<(XQUADS + WQUADS) / 256, 256>>>(x, Wqkv);
    qkv_gemm<<<dim3(E3_ / 128, 4096 / 128), 256>>>(te, Wt);
    attn_kernel<<<dim3(L_, H_, B_), 256, sizeof(AttnSmem)>>>(pos, mask, emb, out);
}

// round 5
// speedup vs baseline: 2.5956x; 2.0405x over previous
#include <cuda_runtime.h>
#include <cuda_bf16.h>
#include <math.h>
#include <stdint.h>

#define B_    4
#define L_    16
#define D_    512
#define H_    8
#define HD_   64
#define NTOK_ 1024
#define E3_   1536

// Scratch (allocation-free rule: __device__ globals)
__device__ float g_Q[B_ * H_ * NTOK_ * HD_];
__device__ float g_K[B_ * H_ * NTOK_ * HD_];
__device__ float g_V[B_ * H_ * NTOK_ * HD_];
__device__ __nv_bfloat16 g_Xhi[4096 * 512];
__device__ __nv_bfloat16 g_Xlo[4096 * 512];
__device__ __nv_bfloat16 g_Whi[1536 * 512];
__device__ __nv_bfloat16 g_Wlo[1536 * 512];

__device__ __forceinline__ uint32_t smem_u32(const void* p) {
    uint32_t a;
    asm("{ .reg .u64 t; cvta.to.shared.u64 t, %1; cvt.u32.u64 %0, t; }" : "=r"(a) : "l"(p));
    return a;
}
__device__ __forceinline__ void ldsm4(uint32_t* r, uint32_t addr) {
    asm volatile("ldmatrix.sync.aligned.m8n8.x4.shared.b16 {%0,%1,%2,%3}, [%4];"
        : "=r"(r[0]), "=r"(r[1]), "=r"(r[2]), "=r"(r[3]) : "r"(addr));
}
__device__ __forceinline__ void ldsm4t(uint32_t* r, uint32_t addr) {
    asm volatile("ldmatrix.sync.aligned.m8n8.x4.trans.shared.b16 {%0,%1,%2,%3}, [%4];"
        : "=r"(r[0]), "=r"(r[1]), "=r"(r[2]), "=r"(r[3]) : "r"(addr));
}
__device__ __forceinline__ void mma16816(float* c, const uint32_t* a, uint32_t b0, uint32_t b1) {
    asm volatile("mma.sync.aligned.m16n8k16.row.col.f32.bf16.bf16.f32 "
        "{%0,%1,%2,%3}, {%4,%5,%6,%7}, {%8,%9}, {%0,%1,%2,%3};"
        : "+f"(c[0]), "+f"(c[1]), "+f"(c[2]), "+f"(c[3])
        : "r"(a[0]), "r"(a[1]), "r"(a[2]), "r"(a[3]), "r"(b0), "r"(b1));
}
__device__ __forceinline__ uint32_t packbf2(float a, float b) {
    __nv_bfloat162 t = __floats2bfloat162_rn(a, b);
    return *reinterpret_cast<uint32_t*>(&t);
}

// ---------------------------------------------------------------------------
// Kernel 0: split X and W into bf16 (hi, lo) pairs.
// ---------------------------------------------------------------------------
#define XQUADS 524288   // 4096*512/4
#define WQUADS 196608   // 1536*512/4

__global__ __launch_bounds__(256) void split_kernel(const float* __restrict__ x,
                                                    const float* __restrict__ W) {
    int i = blockIdx.x * 256 + threadIdx.x;
    const float4* src;
    __nv_bfloat16 *hi, *lo;
    int idx;
    if (i < XQUADS) { src = (const float4*)x; hi = g_Xhi; lo = g_Xlo; idx = i; }
    else            { src = (const float4*)W; hi = g_Whi; lo = g_Wlo; idx = i - XQUADS; }
    float4 v = src[idx];
    float f[4] = {v.x, v.y, v.z, v.w};
    __nv_bfloat162* hp = (__nv_bfloat162*)hi;
    __nv_bfloat162* lp = (__nv_bfloat162*)lo;
#pragma unroll
    for (int j = 0; j < 2; j++) {
        __nv_bfloat16 h0 = __float2bfloat16_rn(f[2 * j]);
        __nv_bfloat16 h1 = __float2bfloat16_rn(f[2 * j + 1]);
        __nv_bfloat16 l0 = __float2bfloat16_rn(f[2 * j] - __bfloat162float(h0));
        __nv_bfloat16 l1 = __float2bfloat16_rn(f[2 * j + 1] - __bfloat162float(h1));
        hp[idx * 2 + j] = __halves2bfloat162(h0, h1);
        lp[idx * 2 + j] = __halves2bfloat162(l0, l1);
    }
}

// ---------------------------------------------------------------------------
// Kernel 1: QKV GEMM via bf16 mma.sync, K' = 1536 (unchanged, passing)
// ---------------------------------------------------------------------------
__global__ __launch_bounds__(256, 2) void qkv_gemm(const float* __restrict__ te,
                                                   const float* __restrict__ Wt) {
    __shared__ __align__(16) uint8_t sAbuf[2][128 * 64];
    __shared__ __align__(16) uint8_t sBbuf[2][128 * 64];
    __shared__ float s_tq[128];

    int tid = threadIdx.x;
    int m0 = blockIdx.y * 128, e0 = blockIdx.x * 128;
    int bb = m0 >> 10, l0 = (m0 >> 6) & 15, third = e0 >> 9;

    {
        int outi = tid >> 1, half = tid & 1;
        int fr = outi >> 6, hd = outi & 63;
        const float4* tp = (const float4*)(te + (size_t)(bb * 16 + l0 + fr) * D_) + half * 64;
        const float4* wp = (const float4*)(Wt + (size_t)(third * 64 + hd) * D_) + half * 64;
        float acc = 0.f;
#pragma unroll 8
        for (int k = 0; k < 64; k++) {
            float4 a = tp[k], w = wp[k];
            acc += a.x * w.x + a.y * w.y + a.z * w.z + a.w * w.w;
        }
        acc += __shfl_xor_sync(0xffffffffu, acc, 1);
        if (!half) s_tq[outi] = acc;
    }

    uint32_t aBase = smem_u32(sAbuf), bBase = smem_u32(sBbuf);

    int mld = tid >> 1;
    int kc0 = (tid & 1) * 2;
    int swm = (mld >> 1) & 3;
    uint32_t dA0 = aBase + mld * 64, dB0 = bBase + mld * 64;
    const __nv_bfloat16* Asrc = g_Xhi + (size_t)(m0 + mld) * 512;
    const __nv_bfloat16* Alo  = g_Xlo + (size_t)(m0 + mld) * 512;
    const __nv_bfloat16* Bsrc = g_Whi + (size_t)(e0 + mld) * 512;
    const __nv_bfloat16* Blo  = g_Wlo + (size_t)(e0 + mld) * 512;

    int lane = tid & 31, warp = tid >> 5;
    int wm = warp & 1, wn = warp >> 1;
    uint32_t aAddr[4]; int aXor[4];
    int rA = lane & 15, kcbA = lane >> 4;
    {
#pragma unroll
        for (int im = 0; im < 4; im++) {
            int mr = wm * 64 + im * 16 + rA;
            aAddr[im] = aBase + mr * 64;
            aXor[im] = (mr >> 1) & 3;
        }
    }
    uint32_t bAddr[2]; int bXor[2];
    int kcbB = (lane >> 3) & 1;
    {
#pragma unroll
        for (int p = 0; p < 2; p++) {
            int nr = wn * 32 + p * 16 + (lane & 7) + ((lane >> 4) << 3);
            bAddr[p] = bBase + nr * 64;
            bXor[p] = (nr >> 1) & 3;
        }
    }

    float c[4][4][4] = {};

#define ISSUE(ki) do {                                                          \
    int _r = (ki) >> 4, _kb = ((ki) & 15) * 32, _st = (ki) & 1;                 \
    const __nv_bfloat16* _ap = (_r == 1) ? Alo : Asrc;                          \
    const __nv_bfloat16* _bp = (_r == 2) ? Blo : Bsrc;                          \
    _Pragma("unroll")                                                           \
    for (int _j = 0; _j < 2; _j++) {                                            \
        int _kc = kc0 + _j;                                                     \
        const void* _sa = _ap + _kb + _kc * 8;                                  \
        const void* _sb = _bp + _kb + _kc * 8;                                  \
        uint32_t _da = dA0 + _st * 8192 + (((_kc) ^ swm) << 4);                 \
        uint32_t _db = dB0 + _st * 8192 + (((_kc) ^ swm) << 4);                 \
        asm volatile("cp.async.cg.shared.global [%0], [%1], 16;" :: "r"(_da), "l"(_sa)); \
        asm volatile("cp.async.cg.shared.global [%0], [%1], 16;" :: "r"(_db), "l"(_sb)); \
    }                                                                           \
    asm volatile("cp.async.commit_group;");                                     \
} while (0)

    ISSUE(0);
    for (int ki = 0; ki < 48; ki++) {
        if (ki + 1 < 48) {
            ISSUE(ki + 1);
            asm volatile("cp.async.wait_group 1;" ::: "memory");
        } else {
            asm volatile("cp.async.wait_group 0;" ::: "memory");
        }
        __syncthreads();
        int st = ki & 1;
#pragma unroll
        for (int s = 0; s < 2; s++) {
            uint32_t a[4][4];
#pragma unroll
            for (int im = 0; im < 4; im++)
                ldsm4(a[im], aAddr[im] + st * 8192 + (((kcbA + 2 * s) ^ aXor[im]) << 4));
            uint32_t bq[2][4];
#pragma unroll
            for (int p = 0; p < 2; p++)
                ldsm4(bq[p], bAddr[p] + st * 8192 + (((kcbB + 2 * s) ^ bXor[p]) << 4));
#pragma unroll
            for (int im = 0; im < 4; im++)
#pragma unroll
                for (int in = 0; in < 4; in++)
                    mma16816(c[im][in], a[im], bq[in >> 1][(in & 1) * 2], bq[in >> 1][(in & 1) * 2 + 1]);
        }
        __syncthreads();
    }

    const float inv_scale = 0.044194173824159216f;  // 1/sqrt(512)
    int gid = lane >> 2, tig = lane & 3;
    float* dst = (third == 0) ? g_Q : ((third == 1) ? g_K : g_V);
#pragma unroll
    for (int im = 0; im < 4; im++) {
#pragma unroll
        for (int hrow = 0; hrow < 2; hrow++) {
            int row = m0 + wm * 64 + im * 16 + gid + hrow * 8;
            int b = row >> 10, l = (row >> 6) & 15, nt = row & 63;
            int frl = (row >> 6) & 1;
#pragma unroll
            for (int in = 0; in < 4; in++) {
                int e = e0 + wn * 32 + in * 8 + 2 * tig;
                int h = (e >> 6) & 7, hd = e & 63;
                float v0 = c[im][in][2 * hrow + 0] + s_tq[frl * 64 + hd];
                float v1 = c[im][in][2 * hrow + 1] + s_tq[frl * 64 + hd + 1];
                if (third == 0) { v0 *= inv_scale; v1 *= inv_scale; }
                float2 vv = make_float2(v0, v1);
                *(float2*)(dst + (size_t)((b * H_ + h) * NTOK_ + l * 64 + nt) * HD_ + hd) = vv;
            }
        }
    }
}

// ---------------------------------------------------------------------------
// Kernel 2: tensor-core fused attention.
// Block = (ql, h, b), 128 threads (4 warps, each owns 16 q-rows).
// QK^T and PV via bf16 mma.sync with hi/lo split (3 terms each).
// Softmax fully register-resident (rows owned by 4-lane groups).
// ---------------------------------------------------------------------------
struct AttnSmem {
    float Qs[64][68];
    __nv_bfloat16 Qhi[64][72];
    __nv_bfloat16 Qlo[64][72];
    __nv_bfloat16 Khi[64][72];
    __nv_bfloat16 Klo[64][72];
    __nv_bfloat16 Vhi[64][72];
    __nv_bfloat16 Vlo[64][72];
    float Et[16][68];
    float bias[64][17];
};

extern __shared__ char smem_raw[];

__global__ __launch_bounds__(128) void attn_kernel(const int* __restrict__ pos,
                                                   const int* __restrict__ mask,
                                                   const float* __restrict__ emb,
                                                   float* __restrict__ out) {
    AttnSmem& s = *reinterpret_cast<AttnSmem*>(smem_raw);
    int ql = blockIdx.x, h = blockIdx.y, b = blockIdx.z;
    int tid = threadIdx.x;
    int lane = tid & 31, w = tid >> 5;
    int r0 = w * 16;

    // ---- load Q fp32, Et
    const float* Qg = g_Q + ((b * H_ + h) * NTOK_ + ql * 64) * HD_;
    for (int i = tid; i < 1024; i += 128) {
        int r = i >> 4, c = (i & 15) << 2;
        *(float4*)&s.Qs[r][c] = *(const float4*)(Qg + r * HD_ + c);
    }
    for (int i = tid; i < 1024; i += 128) {
        int kl = i >> 6, c = i & 63;
        int p = pos[(b * L_ + ql) * L_ + kl];
        p = min(max(p, -8), 8) + 8;
        s.Et[kl][c] = emb[p * HD_ + c];
    }
    __syncthreads();

    // ---- bias[r][kl] = Qrow . Et[kl]  (fp32, 8 dots per thread)
#pragma unroll
    for (int u = 0; u < 8; u++) {
        int id = tid + u * 128;
        int r = id >> 4, kl = id & 15;
        float acc = 0.f;
        const float* qrow = s.Qs[r];
        const float* erow = s.Et[kl];
#pragma unroll 16
        for (int c = 0; c < 64; c++) acc += qrow[c] * erow[c];
        s.bias[r][kl] = acc;
    }
    // ---- convert Q -> hi/lo bf16 tiles
    for (int i = tid; i < 1024; i += 128) {
        int r = i >> 4, c = (i & 15) << 2;
        float4 v = *(const float4*)&s.Qs[r][c];
        __nv_bfloat16 h0 = __float2bfloat16_rn(v.x), h1 = __float2bfloat16_rn(v.y);
        __nv_bfloat16 h2 = __float2bfloat16_rn(v.z), h3 = __float2bfloat16_rn(v.w);
        *(uint32_t*)&s.Qhi[r][c]     = packbf2(__bfloat162float(h0), __bfloat162float(h1));
        *(uint32_t*)&s.Qhi[r][c + 2] = packbf2(__bfloat162float(h2), __bfloat162float(h3));
        *(uint32_t*)&s.Qlo[r][c]     = packbf2(v.x - __bfloat162float(h0), v.y - __bfloat162float(h1));
        *(uint32_t*)&s.Qlo[r][c + 2] = packbf2(v.z - __bfloat162float(h2), v.w - __bfloat162float(h3));
    }
    __syncthreads();

    // ---- Q A-fragments (registers, once)
    uint32_t qh[4][4], qlr[4][4];
    {
        int lrow = (lane & 7) + 8 * ((lane >> 3) & 1);
        int lcol = 8 * (lane >> 4);
#pragma unroll
        for (int kt = 0; kt < 4; kt++) {
            ldsm4(qh[kt],  smem_u32(&s.Qhi[r0 + lrow][kt * 16 + lcol]));
            ldsm4(qlr[kt], smem_u32(&s.Qlo[r0 + lrow][kt * 16 + lcol]));
        }
    }

    int g4 = lane >> 2;             // row-in-8 group
    float m0r = -INFINITY, m1r = -INFINITY, l0r = 0.f, l1r = 0.f;
    float O[8][4] = {};

    int klrow = (lane & 7) + 8 * (lane >> 4);       // K ldsm: n-row component
    int klcol = 8 * ((lane >> 3) & 1);              // K ldsm: k component
    int vlrow = (lane & 7) + 8 * ((lane >> 3) & 1); // V ldsm: k component
    int vlcol = 8 * (lane >> 4);                    // V ldsm: n component

    for (int kl = 0; kl < L_; kl++) {
        if (mask[(b * L_ + ql) * L_ + kl] == 0) continue;

        // ---- load K,V fp32 -> hi/lo bf16 smem
        const float* Kg = g_K + ((b * H_ + h) * NTOK_ + kl * 64) * HD_;
        const float* Vg = g_V + ((b * H_ + h) * NTOK_ + kl * 64) * HD_;
        for (int i = tid; i < 1024; i += 128) {
            int r = i >> 4, c = (i & 15) << 2;
            float4 kv = *(const float4*)(Kg + r * HD_ + c);
            float4 vv = *(const float4*)(Vg + r * HD_ + c);
            __nv_bfloat16 a0 = __float2bfloat16_rn(kv.x), a1 = __float2bfloat16_rn(kv.y);
            __nv_bfloat16 a2 = __float2bfloat16_rn(kv.z), a3 = __float2bfloat16_rn(kv.w);
            *(uint32_t*)&s.Khi[r][c]     = packbf2(__bfloat162float(a0), __bfloat162float(a1));
            *(uint32_t*)&s.Khi[r][c + 2] = packbf2(__bfloat162float(a2), __bfloat162float(a3));
            *(uint32_t*)&s.Klo[r][c]     = packbf2(kv.x - __bfloat162float(a0), kv.y - __bfloat162float(a1));
            *(uint32_t*)&s.Klo[r][c + 2] = packbf2(kv.z - __bfloat162float(a2), kv.w - __bfloat162float(a3));
            __nv_bfloat16 b0 = __float2bfloat16_rn(vv.x), b1 = __float2bfloat16_rn(vv.y);
            __nv_bfloat16 b2 = __float2bfloat16_rn(vv.z), b3 = __float2bfloat16_rn(vv.w);
            *(uint32_t*)&s.Vhi[r][c]     = packbf2(__bfloat162float(b0), __bfloat162float(b1));
            *(uint32_t*)&s.Vhi[r][c + 2] = packbf2(__bfloat162float(b2), __bfloat162float(b3));
            *(uint32_t*)&s.Vlo[r][c]     = packbf2(vv.x - __bfloat162float(b0), vv.y - __bfloat162float(b1));
            *(uint32_t*)&s.Vlo[r][c + 2] = packbf2(vv.z - __bfloat162float(b2), vv.w - __bfloat162float(b3));
        }
        __syncthreads();

        // ---- S = bias + Q.K^T  (3-term split)
        float S[8][4];
        float bb0 = s.bias[r0 + g4][kl], bb1 = s.bias[r0 + 8 + g4][kl];
#pragma unroll
        for (int nt = 0; nt < 8; nt++) {
            S[nt][0] = bb0; S[nt][1] = bb0; S[nt][2] = bb1; S[nt][3] = bb1;
        }
#pragma unroll
        for (int kt = 0; kt < 4; kt++) {
#pragma unroll
            for (int np = 0; np < 4; np++) {
                uint32_t kh[4], klo2[4];
                ldsm4(kh,   smem_u32(&s.Khi[np * 16 + klrow][kt * 16 + klcol]));
                ldsm4(klo2, smem_u32(&s.Klo[np * 16 + klrow][kt * 16 + klcol]));
                mma16816(S[2 * np],     qh[kt],  kh[0],   kh[1]);
                mma16816(S[2 * np + 1], qh[kt],  kh[2],   kh[3]);
                mma16816(S[2 * np],     qlr[kt], kh[0],   kh[1]);
                mma16816(S[2 * np + 1], qlr[kt], kh[2],   kh[3]);
                mma16816(S[2 * np],     qh[kt],  klo2[0], klo2[1]);
                mma16816(S[2 * np + 1], qh[kt],  klo2[2], klo2[3]);
            }
        }

        // ---- online softmax (rows owned by 4-lane groups)
        float mx0 = -INFINITY, mx1 = -INFINITY;
#pragma unroll
        for (int nt = 0; nt < 8; nt++) {
            mx0 = fmaxf(mx0, fmaxf(S[nt][0], S[nt][1]));
            mx1 = fmaxf(mx1, fmaxf(S[nt][2], S[nt][3]));
        }
        mx0 = fmaxf(mx0, __shfl_xor_sync(0xffffffffu, mx0, 1));
        mx0 = fmaxf(mx0, __shfl_xor_sync(0xffffffffu, mx0, 2));
        mx1 = fmaxf(mx1, __shfl_xor_sync(0xffffffffu, mx1, 1));
        mx1 = fmaxf(mx1, __shfl_xor_sync(0xffffffffu, mx1, 2));
        float mn0 = fmaxf(m0r, mx0), mn1 = fmaxf(m1r, mx1);
        float corr0 = __expf(m0r - mn0), corr1 = __expf(m1r - mn1);
        float sum0 = 0.f, sum1 = 0.f;
#pragma unroll
        for (int nt = 0; nt < 8; nt++) {
            S[nt][0] = __expf(S[nt][0] - mn0); S[nt][1] = __expf(S[nt][1] - mn0);
            S[nt][2] = __expf(S[nt][2] - mn1); S[nt][3] = __expf(S[nt][3] - mn1);
            sum0 += S[nt][0] + S[nt][1];
            sum1 += S[nt][2] + S[nt][3];
        }
        sum0 += __shfl_xor_sync(0xffffffffu, sum0, 1);
        sum0 += __shfl_xor_sync(0xffffffffu, sum0, 2);
        sum1 += __shfl_xor_sync(0xffffffffu, sum1, 1);
        sum1 += __shfl_xor_sync(0xffffffffu, sum1, 2);
        l0r = l0r * corr0 + sum0; m0r = mn0;
        l1r = l1r * corr1 + sum1; m1r = mn1;

        // ---- P hi/lo A-fragments from S registers
        uint32_t ph[4][4], pl[4][4];
#pragma unroll
        for (int kt = 0; kt < 4; kt++) {
#pragma unroll
            for (int q = 0; q < 4; q++) {
                int nt = 2 * kt + (q >> 1);
                float x0 = S[nt][(q & 1) * 2], x1 = S[nt][(q & 1) * 2 + 1];
                __nv_bfloat16 hx0 = __float2bfloat16_rn(x0), hx1 = __float2bfloat16_rn(x1);
                ph[kt][q] = *(uint32_t*)&(__nv_bfloat162&)*(&hx0), ph[kt][q] = 0; // placeholder fix below
                __nv_bfloat162 hp2 = __halves2bfloat162(hx0, hx1);
                ph[kt][q] = *(uint32_t*)&hp2;
                __nv_bfloat162 lp2 = __floats2bfloat162_rn(x0 - __bfloat162float(hx0),
                                                           x1 - __bfloat162float(hx1));
                pl[kt][q] = *(uint32_t*)&lp2;
            }
        }

        // ---- O = O*corr + P.V (3-term split)
#pragma unroll
        for (int nt = 0; nt < 8; nt++) {
            O[nt][0] *= corr0; O[nt][1] *= corr0; O[nt][2] *= corr1; O[nt][3] *= corr1;
        }
#pragma unroll
        for (int kt = 0; kt < 4; kt++) {
#pragma unroll
            for (int np = 0; np < 4; np++) {
                uint32_t vh[4], vl[4];
                ldsm4t(vh, smem_u32(&s.Vhi[kt * 16 + vlrow][np * 16 + vlcol]));
                ldsm4t(vl, smem_u32(&s.Vlo[kt * 16 + vlrow][np * 16 + vlcol]));
                mma16816(O[2 * np],     ph[kt], vh[0], vh[1]);
                mma16816(O[2 * np + 1], ph[kt], vh[2], vh[3]);
                mma16816(O[2 * np],     pl[kt], vh[0], vh[1]);
                mma16816(O[2 * np + 1], pl[kt], vh[2], vh[3]);
                mma16816(O[2 * np],     ph[kt], vl[0], vl[1]);
                mma16816(O[2 * np + 1], ph[kt], vl[2], vl[3]);
            }
        }
        __syncthreads();
    }

    // ---- finalize, store
    float inv0 = 1.f / l0r, inv1 = 1.f / l1r;
    int ra = ql * 64 + r0 + g4;
    int colb = h * HD_ + 2 * (lane & 3);
    float* ob = out + (size_t)((b * L_) * 64 + ra) * D_ + colb;
#pragma unroll
    for (int nt = 0; nt < 8; nt++) {
        *(float2*)(ob + nt * 8)            = make_float2(O[nt][0] * inv0, O[nt][1] * inv0);
        *(float2*)(ob + 8 * D_ + nt * 8)   = make_float2(O[nt][2] * inv1, O[nt][3] * inv1);
    }
}

// ---------------------------------------------------------------------------
extern "C" void kernel_launch(void* const* d_in, const int* in_sizes, int n_in,
                              void* d_out, int out_size) {
    const float* x    = (const float*)d_in[0];
    const float* te   = (const float*)d_in[1];
    const int*   pos  = (const int*)d_in[2];
    const int*   mask = (const int*)d_in[3];
    const float* Wqkv = (const float*)d_in[4];
    const float* Wt   = (const float*)d_in[5];
    const float* emb  = (const float*)d_in[6];
    float* out = (float*)d_out;

    cudaFuncSetAttribute(attn_kernel, cudaFuncAttributeMaxDynamicSharedMemorySize,
                         (int)sizeof(AttnSmem));

    split_kernel<<<(XQUADS + WQUADS) / 256, 256>>>(x, Wqkv);
    qkv_gemm<<<dim3(E3_ / 128, 4096 / 128), 256>>>(te, Wt);
    attn_kernel<<<dim3(L_, H_, B_), 128, sizeof(AttnSmem)>>>(pos, mask, emb, out);
}

// round 6
// speedup vs baseline: 3.0574x; 1.1779x over previous
#include <cuda_runtime.h>
#include <cuda_bf16.h>
#include <math.h>
#include <stdint.h>

#define B_    4
#define L_    16
#define D_    512
#define H_    8
#define HD_   64
#define NTOK_ 1024
#define E3_   1536

// Scratch (allocation-free rule: __device__ globals)
__device__ float g_Q[B_ * H_ * NTOK_ * HD_];
__device__ __nv_bfloat16 g_Khi[B_ * H_ * NTOK_ * HD_];
__device__ __nv_bfloat16 g_Klo[B_ * H_ * NTOK_ * HD_];
__device__ __nv_bfloat16 g_Vhi[B_ * H_ * NTOK_ * HD_];
__device__ __nv_bfloat16 g_Vlo[B_ * H_ * NTOK_ * HD_];
__device__ __nv_bfloat16 g_Xhi[4096 * 512];
__device__ __nv_bfloat16 g_Xlo[4096 * 512];
__device__ __nv_bfloat16 g_Whi[1536 * 512];
__device__ __nv_bfloat16 g_Wlo[1536 * 512];

__device__ __forceinline__ uint32_t smem_u32(const void* p) {
    uint32_t a;
    asm("{ .reg .u64 t; cvta.to.shared.u64 t, %1; cvt.u32.u64 %0, t; }" : "=r"(a) : "l"(p));
    return a;
}
__device__ __forceinline__ void ldsm4(uint32_t* r, uint32_t addr) {
    asm volatile("ldmatrix.sync.aligned.m8n8.x4.shared.b16 {%0,%1,%2,%3}, [%4];"
        : "=r"(r[0]), "=r"(r[1]), "=r"(r[2]), "=r"(r[3]) : "r"(addr));
}
__device__ __forceinline__ void ldsm4t(uint32_t* r, uint32_t addr) {
    asm volatile("ldmatrix.sync.aligned.m8n8.x4.trans.shared.b16 {%0,%1,%2,%3}, [%4];"
        : "=r"(r[0]), "=r"(r[1]), "=r"(r[2]), "=r"(r[3]) : "r"(addr));
}
__device__ __forceinline__ void mma16816(float* c, const uint32_t* a, uint32_t b0, uint32_t b1) {
    asm volatile("mma.sync.aligned.m16n8k16.row.col.f32.bf16.bf16.f32 "
        "{%0,%1,%2,%3}, {%4,%5,%6,%7}, {%8,%9}, {%0,%1,%2,%3};"
        : "+f"(c[0]), "+f"(c[1]), "+f"(c[2]), "+f"(c[3])
        : "r"(a[0]), "r"(a[1]), "r"(a[2]), "r"(a[3]), "r"(b0), "r"(b1));
}
__device__ __forceinline__ uint32_t packbf2(float a, float b) {
    __nv_bfloat162 t = __floats2bfloat162_rn(a, b);
    return *reinterpret_cast<uint32_t*>(&t);
}

extern __shared__ char smem_raw[];

// ---------------------------------------------------------------------------
// Kernel 0: split X and W into bf16 (hi, lo) pairs.
// ---------------------------------------------------------------------------
#define XQUADS 524288   // 4096*512/4
#define WQUADS 196608   // 1536*512/4

__global__ __launch_bounds__(256) void split_kernel(const float* __restrict__ x,
                                                    const float* __restrict__ W) {
    int i = blockIdx.x * 256 + threadIdx.x;
    const float4* src;
    __nv_bfloat16 *hi, *lo;
    int idx;
    if (i < XQUADS) { src = (const float4*)x; hi = g_Xhi; lo = g_Xlo; idx = i; }
    else            { src = (const float4*)W; hi = g_Whi; lo = g_Wlo; idx = i - XQUADS; }
    float4 v = src[idx];
    float f[4] = {v.x, v.y, v.z, v.w};
    __nv_bfloat162* hp = (__nv_bfloat162*)hi;
    __nv_bfloat162* lp = (__nv_bfloat162*)lo;
#pragma unroll
    for (int j = 0; j < 2; j++) {
        __nv_bfloat16 h0 = __float2bfloat16_rn(f[2 * j]);
        __nv_bfloat16 h1 = __float2bfloat16_rn(f[2 * j + 1]);
        __nv_bfloat16 l0 = __float2bfloat16_rn(f[2 * j] - __bfloat162float(h0));
        __nv_bfloat16 l1 = __float2bfloat16_rn(f[2 * j + 1] - __bfloat162float(h1));
        hp[idx * 2 + j] = __halves2bfloat162(h0, h1);
        lp[idx * 2 + j] = __halves2bfloat162(l0, l1);
    }
}

// ---------------------------------------------------------------------------
// Kernel 1: QKV GEMM via bf16 mma.sync, K' = 1536, 3-stage cp.async ring.
// Epilogue: +tqkv; Q -> fp32 g_Q (pre-scaled); K,V -> bf16 hi/lo arrays.
// ---------------------------------------------------------------------------
#define GEMM_SMEM (6 * 8192 + 512)

__global__ __launch_bounds__(256, 2) void qkv_gemm(const float* __restrict__ te,
                                                   const float* __restrict__ Wt) {
    uint32_t aBase = smem_u32(smem_raw);
    uint32_t bBase = aBase + 3 * 8192;
    float* s_tq = (float*)(smem_raw + 6 * 8192);

    int tid = threadIdx.x;
    int m0 = blockIdx.y * 128, e0 = blockIdx.x * 128;
    int bb = m0 >> 10, l0 = (m0 >> 6) & 15, third = e0 >> 9;

    // in-block tqkv
    {
        int outi = tid >> 1, half = tid & 1;
        int fr = outi >> 6, hd = outi & 63;
        const float4* tp = (const float4*)(te + (size_t)(bb * 16 + l0 + fr) * D_) + half * 64;
        const float4* wp = (const float4*)(Wt + (size_t)(third * 64 + hd) * D_) + half * 64;
        float acc = 0.f;
#pragma unroll 8
        for (int k = 0; k < 64; k++) {
            float4 a = tp[k], w = wp[k];
            acc += a.x * w.x + a.y * w.y + a.z * w.z + a.w * w.w;
        }
        acc += __shfl_xor_sync(0xffffffffu, acc, 1);
        if (!half) s_tq[outi] = acc;
    }

    int mld = tid >> 1;
    int kc0 = (tid & 1) * 2;
    int swm = (mld >> 1) & 3;
    uint32_t dA0 = aBase + mld * 64, dB0 = bBase + mld * 64;
    const __nv_bfloat16* Asrc = g_Xhi + (size_t)(m0 + mld) * 512;
    const __nv_bfloat16* Alo  = g_Xlo + (size_t)(m0 + mld) * 512;
    const __nv_bfloat16* Bsrc = g_Whi + (size_t)(e0 + mld) * 512;
    const __nv_bfloat16* Blo  = g_Wlo + (size_t)(e0 + mld) * 512;

    int lane = tid & 31, warp = tid >> 5;
    int wm = warp & 1, wn = warp >> 1;
    uint32_t aAddr[4]; int aXor[4];
    int rA = lane & 15, kcbA = lane >> 4;
#pragma unroll
    for (int im = 0; im < 4; im++) {
        int mr = wm * 64 + im * 16 + rA;
        aAddr[im] = aBase + mr * 64;
        aXor[im] = (mr >> 1) & 3;
    }
    uint32_t bAddr[2]; int bXor[2];
    int kcbB = (lane >> 3) & 1;
#pragma unroll
    for (int p = 0; p < 2; p++) {
        int nr = wn * 32 + p * 16 + (lane & 7) + ((lane >> 4) << 3);
        bAddr[p] = bBase + nr * 64;
        bXor[p] = (nr >> 1) & 3;
    }

    float c[4][4][4] = {};

#define ISSUE(ki, st) do {                                                      \
    int _r = (ki) >> 4, _kb = ((ki) & 15) * 32;                                 \
    const __nv_bfloat16* _ap = (_r == 1) ? Alo : Asrc;                          \
    const __nv_bfloat16* _bp = (_r == 2) ? Blo : Bsrc;                          \
    _Pragma("unroll")                                                           \
    for (int _j = 0; _j < 2; _j++) {                                            \
        int _kc = kc0 + _j;                                                     \
        const void* _sa = _ap + _kb + _kc * 8;                                  \
        const void* _sb = _bp + _kb + _kc * 8;                                  \
        uint32_t _da = dA0 + (st) * 8192 + (((_kc) ^ swm) << 4);                \
        uint32_t _db = dB0 + (st) * 8192 + (((_kc) ^ swm) << 4);                \
        asm volatile("cp.async.cg.shared.global [%0], [%1], 16;" :: "r"(_da), "l"(_sa)); \
        asm volatile("cp.async.cg.shared.global [%0], [%1], 16;" :: "r"(_db), "l"(_sb)); \
    }                                                                           \
    asm volatile("cp.async.commit_group;");                                     \
} while (0)

    ISSUE(0, 0);
    ISSUE(1, 1);
    int cur = 0, nxt = 2;
    for (int ki = 0; ki < 48; ki++) {
        asm volatile("cp.async.wait_group 1;" ::: "memory");
        __syncthreads();
        if (ki + 2 < 48) ISSUE(ki + 2, nxt);
#pragma unroll
        for (int s = 0; s < 2; s++) {
            uint32_t a[4][4];
#pragma unroll
            for (int im = 0; im < 4; im++)
                ldsm4(a[im], aAddr[im] + cur * 8192 + (((kcbA + 2 * s) ^ aXor[im]) << 4));
            uint32_t bq[2][4];
#pragma unroll
            for (int p = 0; p < 2; p++)
                ldsm4(bq[p], bAddr[p] + cur * 8192 + (((kcbB + 2 * s) ^ bXor[p]) << 4));
#pragma unroll
            for (int im = 0; im < 4; im++)
#pragma unroll
                for (int in = 0; in < 4; in++)
                    mma16816(c[im][in], a[im], bq[in >> 1][(in & 1) * 2], bq[in >> 1][(in & 1) * 2 + 1]);
        }
        cur = (cur == 2) ? 0 : cur + 1;
        nxt = (nxt == 2) ? 0 : nxt + 1;
    }

    // epilogue
    const float inv_scale = 0.044194173824159216f;  // 1/sqrt(512)
    int gid = lane >> 2, tig = lane & 3;
#pragma unroll
    for (int im = 0; im < 4; im++) {
#pragma unroll
        for (int hrow = 0; hrow < 2; hrow++) {
            int row = m0 + wm * 64 + im * 16 + gid + hrow * 8;
            int b = row >> 10, l = (row >> 6) & 15, nt = row & 63;
            int frl = (row >> 6) & 1;
#pragma unroll
            for (int in = 0; in < 4; in++) {
                int e = e0 + wn * 32 + in * 8 + 2 * tig;
                int h = (e >> 6) & 7, hd = e & 63;
                float v0 = c[im][in][2 * hrow + 0] + s_tq[frl * 64 + hd];
                float v1 = c[im][in][2 * hrow + 1] + s_tq[frl * 64 + hd + 1];
                size_t off = (size_t)((b * H_ + h) * NTOK_ + l * 64 + nt) * HD_ + hd;
                if (third == 0) {
                    *(float2*)(g_Q + off) = make_float2(v0 * inv_scale, v1 * inv_scale);
                } else {
                    __nv_bfloat16 h0 = __float2bfloat16_rn(v0), h1 = __float2bfloat16_rn(v1);
                    __nv_bfloat162 hv = __halves2bfloat162(h0, h1);
                    __nv_bfloat162 lv = __floats2bfloat162_rn(v0 - __bfloat162float(h0),
                                                              v1 - __bfloat162float(h1));
                    __nv_bfloat162* hiA = (third == 1) ? (__nv_bfloat162*)g_Khi : (__nv_bfloat162*)g_Vhi;
                    __nv_bfloat162* loA = (third == 1) ? (__nv_bfloat162*)g_Klo : (__nv_bfloat162*)g_Vlo;
                    hiA[off >> 1] = hv;
                    loA[off >> 1] = lv;
                }
            }
        }
    }
}

// ---------------------------------------------------------------------------
// Kernel 2: tensor-core fused attention, pre-split K/V via cp.async,
// double-buffered over valid (masked-in) key frames.
// Block = (ql, h, b), 128 threads.
// smem layout (bytes):
//   KV[2][4][8192]  : 65536   (stage, tile{Khi,Klo,Vhi,Vlo}, 64x64 bf16 swizzled)
//   Qhi[8192] Qlo[8192]       (64x64 bf16 swizzled)
//   Qs[64][68] f32  : 17408
//   Et[16][68] f32  : 4352
//   bias[64][17] f32: 4352
//   list[16] + nv   : 68
// ---------------------------------------------------------------------------
#define ATT_KV     0
#define ATT_QHI    65536
#define ATT_QLO    (ATT_QHI + 8192)
#define ATT_QS     (ATT_QLO + 8192)
#define ATT_ET     (ATT_QS + 64 * 68 * 4)
#define ATT_BIAS   (ATT_ET + 16 * 68 * 4)
#define ATT_LIST   (ATT_BIAS + 64 * 17 * 4)
#define ATT_SMEM   (ATT_LIST + 68)

__global__ __launch_bounds__(128) void attn_kernel(const int* __restrict__ pos,
                                                   const int* __restrict__ mask,
                                                   const float* __restrict__ emb,
                                                   float* __restrict__ out) {
    uint32_t sbase = smem_u32(smem_raw);
    float (*Qs)[68] = (float(*)[68])(smem_raw + ATT_QS);
    float (*Et)[68] = (float(*)[68])(smem_raw + ATT_ET);
    float (*bias)[17] = (float(*)[17])(smem_raw + ATT_BIAS);
    int* list = (int*)(smem_raw + ATT_LIST);

    int ql = blockIdx.x, h = blockIdx.y, b = blockIdx.z;
    int tid = threadIdx.x;
    int lane = tid & 31, w = tid >> 5;
    int r0 = w * 16;
    int bh = b * H_ + h;

    // ---- valid-frame list
    if (tid == 0) {
        int nv = 0;
        const int* mrow = mask + (b * L_ + ql) * L_;
#pragma unroll
        for (int kl = 0; kl < L_; kl++)
            if (mrow[kl] != 0) list[nv++] = kl;
        list[16] = nv;
    }

    // ---- load Q fp32, Et
    const float* Qg = g_Q + ((size_t)bh * NTOK_ + ql * 64) * HD_;
    for (int i = tid; i < 1024; i += 128) {
        int r = i >> 4, c = (i & 15) << 2;
        *(float4*)&Qs[r][c] = *(const float4*)(Qg + r * HD_ + c);
    }
    for (int i = tid; i < 1024; i += 128) {
        int kl = i >> 6, c = i & 63;
        int p = pos[(b * L_ + ql) * L_ + kl];
        p = min(max(p, -8), 8) + 8;
        Et[kl][c] = emb[p * HD_ + c];
    }
    __syncthreads();
    int nv = list[16];

    // ---- bias[r][kl] = Qrow . Et[kl]
#pragma unroll
    for (int u = 0; u < 8; u++) {
        int id = tid + u * 128;
        int r = id >> 4, kl = id & 15;
        float acc = 0.f;
        const float* qrow = Qs[r];
        const float* erow = Et[kl];
#pragma unroll 16
        for (int c = 0; c < 64; c++) acc += qrow[c] * erow[c];
        bias[r][kl] = acc;
    }

    // ---- convert Q -> hi/lo bf16 swizzled tiles (each thread: 4 chunk pairs)
#pragma unroll
    for (int i = 0; i < 4; i++) {
        int linear = i * 128 + tid;          // 0..511 chunk of hi tile
        int row = linear >> 3, ch = linear & 7;
        const float* qp = &Qs[row][ch * 8];
        uint32_t hi4[4], lo4[4];
#pragma unroll
        for (int j = 0; j < 4; j++) {
            float x0 = qp[2 * j], x1 = qp[2 * j + 1];
            __nv_bfloat16 h0 = __float2bfloat16_rn(x0), h1 = __float2bfloat16_rn(x1);
            hi4[j] = packbf2(__bfloat162float(h0), __bfloat162float(h1));
            lo4[j] = packbf2(x0 - __bfloat162float(h0), x1 - __bfloat162float(h1));
        }
        uint32_t soff = row * 128 + ((ch ^ (row & 7)) << 4);
        *(uint4*)(smem_raw + ATT_QHI + soff) = *(uint4*)hi4;
        *(uint4*)(smem_raw + ATT_QLO + soff) = *(uint4*)lo4;
    }
    __syncthreads();

    // ---- Q A-fragments (registers, once)
    uint32_t qh[4][4], qlr[4][4];
    {
        int lrow = (lane & 7) + 8 * ((lane >> 3) & 1);
        int khalf = lane >> 4;
#pragma unroll
        for (int kt = 0; kt < 4; kt++) {
            int qr = r0 + lrow;
            int qc = kt * 2 + khalf;
            uint32_t off = qr * 128 + ((qc ^ (qr & 7)) << 4);
            ldsm4(qh[kt],  sbase + ATT_QHI + off);
            ldsm4(qlr[kt], sbase + ATT_QLO + off);
        }
    }

    int g4 = lane >> 2;
    float m0r = -INFINITY, m1r = -INFINITY, l0r = 0.f, l1r = 0.f;
    float O[8][4] = {};

    int klrow = (lane & 7) + 8 * (lane >> 4);       // K ldsm n-row component
    int kchalf = (lane >> 3) & 1;                   // K ldsm k 16B-half
    int vlrow = (lane & 7) + 8 * ((lane >> 3) & 1); // V ldsm k component
    int vchalf = lane >> 4;                         // V ldsm n 16B-half

    // per-frame cp.async issue: warp w handles tile w (Khi,Klo,Vhi,Vlo)
    const __nv_bfloat16* tile_src[4] = {
        g_Khi + (size_t)bh * NTOK_ * HD_, g_Klo + (size_t)bh * NTOK_ * HD_,
        g_Vhi + (size_t)bh * NTOK_ * HD_, g_Vlo + (size_t)bh * NTOK_ * HD_
    };
    const __nv_bfloat16* mysrc = tile_src[w];
    uint32_t mydst = sbase + ATT_KV + w * 8192;

#define ISSUE_FRAME(f, stage) do {                                              \
    const __nv_bfloat16* _s = mysrc + (f) * 4096;                               \
    uint32_t _d = mydst + (stage) * 32768;                                      \
    _Pragma("unroll")                                                           \
    for (int _c = 0; _c < 16; _c++) {                                           \
        int _lin = _c * 32 + lane;                                              \
        int _row = _lin >> 3, _ch = _lin & 7;                                   \
        uint32_t _da = _d + _row * 128 + ((_ch ^ (_row & 7)) << 4);             \
        asm volatile("cp.async.cg.shared.global [%0], [%1], 16;"                \
                     :: "r"(_da), "l"(_s + _row * 64 + _ch * 8));               \
    }                                                                           \
    asm volatile("cp.async.commit_group;");                                     \
} while (0)

    ISSUE_FRAME(list[0], 0);

    for (int j = 0; j < nv; j++) {
        int stage = j & 1;
        if (j + 1 < nv) {
            ISSUE_FRAME(list[j + 1], (j + 1) & 1);
            asm volatile("cp.async.wait_group 1;" ::: "memory");
        } else {
            asm volatile("cp.async.wait_group 0;" ::: "memory");
        }
        __syncthreads();
        int kl = list[j];
        uint32_t khiB = sbase + ATT_KV + stage * 32768;
        uint32_t kloB = khiB + 8192;
        uint32_t vhiB = khiB + 16384;
        uint32_t vloB = khiB + 24576;

        // ---- S = bias + Q.K^T (3-term split)
        float S[8][4];
        float bb0 = bias[r0 + g4][kl], bb1 = bias[r0 + 8 + g4][kl];
#pragma unroll
        for (int nt = 0; nt < 8; nt++) {
            S[nt][0] = bb0; S[nt][1] = bb0; S[nt][2] = bb1; S[nt][3] = bb1;
        }
#pragma unroll
        for (int kt = 0; kt < 4; kt++) {
#pragma unroll
            for (int np = 0; np < 4; np++) {
                int nr = np * 16 + klrow;
                int kc = kt * 2 + kchalf;
                uint32_t off = nr * 128 + ((kc ^ (nr & 7)) << 4);
                uint32_t kh[4], klo2[4];
                ldsm4(kh,   khiB + off);
                ldsm4(klo2, kloB + off);
                mma16816(S[2 * np],     qh[kt],  kh[0],   kh[1]);
                mma16816(S[2 * np + 1], qh[kt],  kh[2],   kh[3]);
                mma16816(S[2 * np],     qlr[kt], kh[0],   kh[1]);
                mma16816(S[2 * np + 1], qlr[kt], kh[2],   kh[3]);
                mma16816(S[2 * np],     qh[kt],  klo2[0], klo2[1]);
                mma16816(S[2 * np + 1], qh[kt],  klo2[2], klo2[3]);
            }
        }

        // ---- online softmax
        float mx0 = -INFINITY, mx1 = -INFINITY;
#pragma unroll
        for (int nt = 0; nt < 8; nt++) {
            mx0 = fmaxf(mx0, fmaxf(S[nt][0], S[nt][1]));
            mx1 = fmaxf(mx1, fmaxf(S[nt][2], S[nt][3]));
        }
        mx0 = fmaxf(mx0, __shfl_xor_sync(0xffffffffu, mx0, 1));
        mx0 = fmaxf(mx0, __shfl_xor_sync(0xffffffffu, mx0, 2));
        mx1 = fmaxf(mx1, __shfl_xor_sync(0xffffffffu, mx1, 1));
        mx1 = fmaxf(mx1, __shfl_xor_sync(0xffffffffu, mx1, 2));
        float mn0 = fmaxf(m0r, mx0), mn1 = fmaxf(m1r, mx1);
        float corr0 = __expf(m0r - mn0), corr1 = __expf(m1r - mn1);
        float sum0 = 0.f, sum1 = 0.f;
#pragma unroll
        for (int nt = 0; nt < 8; nt++) {
            S[nt][0] = __expf(S[nt][0] - mn0); S[nt][1] = __expf(S[nt][1] - mn0);
            S[nt][2] = __expf(S[nt][2] - mn1); S[nt][3] = __expf(S[nt][3] - mn1);
            sum0 += S[nt][0] + S[nt][1];
            sum1 += S[nt][2] + S[nt][3];
        }
        sum0 += __shfl_xor_sync(0xffffffffu, sum0, 1);
        sum0 += __shfl_xor_sync(0xffffffffu, sum0, 2);
        sum1 += __shfl_xor_sync(0xffffffffu, sum1, 1);
        sum1 += __shfl_xor_sync(0xffffffffu, sum1, 2);
        l0r = l0r * corr0 + sum0; m0r = mn0;
        l1r = l1r * corr1 + sum1; m1r = mn1;

        // ---- P hi/lo A-fragments
        uint32_t ph[4][4], pl[4][4];
#pragma unroll
        for (int kt = 0; kt < 4; kt++) {
#pragma unroll
            for (int q = 0; q < 4; q++) {
                int nt = 2 * kt + (q >> 1);
                float x0 = S[nt][(q & 1) * 2], x1 = S[nt][(q & 1) * 2 + 1];
                __nv_bfloat16 hx0 = __float2bfloat16_rn(x0), hx1 = __float2bfloat16_rn(x1);
                __nv_bfloat162 hp2 = __halves2bfloat162(hx0, hx1);
                ph[kt][q] = *(uint32_t*)&hp2;
                __nv_bfloat162 lp2 = __floats2bfloat162_rn(x0 - __bfloat162float(hx0),
                                                           x1 - __bfloat162float(hx1));
                pl[kt][q] = *(uint32_t*)&lp2;
            }
        }

        // ---- O = O*corr + P.V (3-term split)
#pragma unroll
        for (int nt = 0; nt < 8; nt++) {
            O[nt][0] *= corr0; O[nt][1] *= corr0; O[nt][2] *= corr1; O[nt][3] *= corr1;
        }
#pragma unroll
        for (int kt = 0; kt < 4; kt++) {
#pragma unroll
            for (int np = 0; np < 4; np++) {
                int vr = kt * 16 + vlrow;
                int vc = np * 2 + vchalf;
                uint32_t off = vr * 128 + ((vc ^ (vr & 7)) << 4);
                uint32_t vh[4], vl[4];
                ldsm4t(vh, vhiB + off);
                ldsm4t(vl, vloB + off);
                mma16816(O[2 * np],     ph[kt], vh[0], vh[1]);
                mma16816(O[2 * np + 1], ph[kt], vh[2], vh[3]);
                mma16816(O[2 * np],     pl[kt], vh[0], vh[1]);
                mma16816(O[2 * np + 1], pl[kt], vh[2], vh[3]);
                mma16816(O[2 * np],     ph[kt], vl[0], vl[1]);
                mma16816(O[2 * np + 1], ph[kt], vl[2], vl[3]);
            }
        }
        __syncthreads();
    }

    // ---- finalize, store
    float inv0 = 1.f / l0r, inv1 = 1.f / l1r;
    int ra = ql * 64 + r0 + g4;
    int colb = h * HD_ + 2 * (lane & 3);
    float* ob = out + (size_t)((b * L_) * 64 + ra) * D_ + colb;
#pragma unroll
    for (int nt = 0; nt < 8; nt++) {
        *(float2*)(ob + nt * 8)          = make_float2(O[nt][0] * inv0, O[nt][1] * inv0);
        *(float2*)(ob + 8 * D_ + nt * 8) = make_float2(O[nt][2] * inv1, O[nt][3] * inv1);
    }
}

// ---------------------------------------------------------------------------
extern "C" void kernel_launch(void* const* d_in, const int* in_sizes, int n_in,
                              void* d_out, int out_size) {
    const float* x    = (const float*)d_in[0];
    const float* te   = (const float*)d_in[1];
    const int*   pos  = (const int*)d_in[2];
    const int*   mask = (const int*)d_in[3];
    const float* Wqkv = (const float*)d_in[4];
    const float* Wt   = (const float*)d_in[5];
    const float* emb  = (const float*)d_in[6];
    float* out = (float*)d_out;

    cudaFuncSetAttribute(qkv_gemm, cudaFuncAttributeMaxDynamicSharedMemorySize, GEMM_SMEM);
    cudaFuncSetAttribute(attn_kernel, cudaFuncAttributeMaxDynamicSharedMemorySize, ATT_SMEM);

    split_kernel<<<(XQUADS + WQUADS) / 256, 256>>>(x, Wqkv);
    qkv_gemm<<<dim3(E3_ / 128, 4096 / 128), 256, GEMM_SMEM>>>(te, Wt);
    attn_kernel<<<dim3(L_, H_, B_), 128, ATT_SMEM>>>(pos, mask, emb, out);
}

// round 7
// speedup vs baseline: 3.1271x; 1.0228x over previous
#include <cuda_runtime.h>
#include <cuda_bf16.h>
#include <math.h>
#include <stdint.h>

#define B_    4
#define L_    16
#define D_    512
#define H_    8
#define HD_   64
#define NTOK_ 1024
#define E3_   1536

// Scratch (allocation-free rule: __device__ globals)
__device__ float g_Q[B_ * H_ * NTOK_ * HD_];
__device__ __nv_bfloat16 g_Khi[B_ * H_ * NTOK_ * HD_];
__device__ __nv_bfloat16 g_Klo[B_ * H_ * NTOK_ * HD_];
__device__ __nv_bfloat16 g_Vhi[B_ * H_ * NTOK_ * HD_];
__device__ __nv_bfloat16 g_Vlo[B_ * H_ * NTOK_ * HD_];
__device__ __nv_bfloat16 g_Xhi[4096 * 512];
__device__ __nv_bfloat16 g_Xlo[4096 * 512];
__device__ __nv_bfloat16 g_Whi[1536 * 512];
__device__ __nv_bfloat16 g_Wlo[1536 * 512];

__device__ __forceinline__ uint32_t smem_u32(const void* p) {
    uint32_t a;
    asm("{ .reg .u64 t; cvta.to.shared.u64 t, %1; cvt.u32.u64 %0, t; }" : "=r"(a) : "l"(p));
    return a;
}
__device__ __forceinline__ void ldsm4(uint32_t* r, uint32_t addr) {
    asm volatile("ldmatrix.sync.aligned.m8n8.x4.shared.b16 {%0,%1,%2,%3}, [%4];"
        : "=r"(r[0]), "=r"(r[1]), "=r"(r[2]), "=r"(r[3]) : "r"(addr));
}
__device__ __forceinline__ void ldsm4t(uint32_t* r, uint32_t addr) {
    asm volatile("ldmatrix.sync.aligned.m8n8.x4.trans.shared.b16 {%0,%1,%2,%3}, [%4];"
        : "=r"(r[0]), "=r"(r[1]), "=r"(r[2]), "=r"(r[3]) : "r"(addr));
}
__device__ __forceinline__ void mma16816(float* c, const uint32_t* a, uint32_t b0, uint32_t b1) {
    asm volatile("mma.sync.aligned.m16n8k16.row.col.f32.bf16.bf16.f32 "
        "{%0,%1,%2,%3}, {%4,%5,%6,%7}, {%8,%9}, {%0,%1,%2,%3};"
        : "+f"(c[0]), "+f"(c[1]), "+f"(c[2]), "+f"(c[3])
        : "r"(a[0]), "r"(a[1]), "r"(a[2]), "r"(a[3]), "r"(b0), "r"(b1));
}
__device__ __forceinline__ uint32_t packbf2(float a, float b) {
    __nv_bfloat162 t = __floats2bfloat162_rn(a, b);
    return *reinterpret_cast<uint32_t*>(&t);
}

extern __shared__ char smem_raw[];

// ---------------------------------------------------------------------------
// Kernel 0: split X and W into bf16 (hi, lo) pairs.
// ---------------------------------------------------------------------------
#define XQUADS 524288   // 4096*512/4
#define WQUADS 196608   // 1536*512/4

__global__ __launch_bounds__(256) void split_kernel(const float* __restrict__ x,
                                                    const float* __restrict__ W) {
    int i = blockIdx.x * 256 + threadIdx.x;
    const float4* src;
    __nv_bfloat16 *hi, *lo;
    int idx;
    if (i < XQUADS) { src = (const float4*)x; hi = g_Xhi; lo = g_Xlo; idx = i; }
    else            { src = (const float4*)W; hi = g_Whi; lo = g_Wlo; idx = i - XQUADS; }
    float4 v = src[idx];
    float f[4] = {v.x, v.y, v.z, v.w};
    __nv_bfloat162* hp = (__nv_bfloat162*)hi;
    __nv_bfloat162* lp = (__nv_bfloat162*)lo;
#pragma unroll
    for (int j = 0; j < 2; j++) {
        __nv_bfloat16 h0 = __float2bfloat16_rn(f[2 * j]);
        __nv_bfloat16 h1 = __float2bfloat16_rn(f[2 * j + 1]);
        __nv_bfloat16 l0 = __float2bfloat16_rn(f[2 * j] - __bfloat162float(h0));
        __nv_bfloat16 l1 = __float2bfloat16_rn(f[2 * j + 1] - __bfloat162float(h1));
        hp[idx * 2 + j] = __halves2bfloat162(h0, h1);
        lp[idx * 2 + j] = __halves2bfloat162(l0, l1);
    }
}

// ---------------------------------------------------------------------------
// Kernel 1: QKV GEMM via bf16 mma.sync, K' = 1536, 3-stage cp.async ring.
// (unchanged from round 6 — passing)
// ---------------------------------------------------------------------------
#define GEMM_SMEM (6 * 8192 + 512)

__global__ __launch_bounds__(256, 2) void qkv_gemm(const float* __restrict__ te,
                                                   const float* __restrict__ Wt) {
    uint32_t aBase = smem_u32(smem_raw);
    uint32_t bBase = aBase + 3 * 8192;
    float* s_tq = (float*)(smem_raw + 6 * 8192);

    int tid = threadIdx.x;
    int m0 = blockIdx.y * 128, e0 = blockIdx.x * 128;
    int bb = m0 >> 10, l0 = (m0 >> 6) & 15, third = e0 >> 9;

    {
        int outi = tid >> 1, half = tid & 1;
        int fr = outi >> 6, hd = outi & 63;
        const float4* tp = (const float4*)(te + (size_t)(bb * 16 + l0 + fr) * D_) + half * 64;
        const float4* wp = (const float4*)(Wt + (size_t)(third * 64 + hd) * D_) + half * 64;
        float acc = 0.f;
#pragma unroll 8
        for (int k = 0; k < 64; k++) {
            float4 a = tp[k], w = wp[k];
            acc += a.x * w.x + a.y * w.y + a.z * w.z + a.w * w.w;
        }
        acc += __shfl_xor_sync(0xffffffffu, acc, 1);
        if (!half) s_tq[outi] = acc;
    }

    int mld = tid >> 1;
    int kc0 = (tid & 1) * 2;
    int swm = (mld >> 1) & 3;
    uint32_t dA0 = aBase + mld * 64, dB0 = bBase + mld * 64;
    const __nv_bfloat16* Asrc = g_Xhi + (size_t)(m0 + mld) * 512;
    const __nv_bfloat16* Alo  = g_Xlo + (size_t)(m0 + mld) * 512;
    const __nv_bfloat16* Bsrc = g_Whi + (size_t)(e0 + mld) * 512;
    const __nv_bfloat16* Blo  = g_Wlo + (size_t)(e0 + mld) * 512;

    int lane = tid & 31, warp = tid >> 5;
    int wm = warp & 1, wn = warp >> 1;
    uint32_t aAddr[4]; int aXor[4];
    int rA = lane & 15, kcbA = lane >> 4;
#pragma unroll
    for (int im = 0; im < 4; im++) {
        int mr = wm * 64 + im * 16 + rA;
        aAddr[im] = aBase + mr * 64;
        aXor[im] = (mr >> 1) & 3;
    }
    uint32_t bAddr[2]; int bXor[2];
    int kcbB = (lane >> 3) & 1;
#pragma unroll
    for (int p = 0; p < 2; p++) {
        int nr = wn * 32 + p * 16 + (lane & 7) + ((lane >> 4) << 3);
        bAddr[p] = bBase + nr * 64;
        bXor[p] = (nr >> 1) & 3;
    }

    float c[4][4][4] = {};

#define ISSUE(ki, st) do {                                                      \
    int _r = (ki) >> 4, _kb = ((ki) & 15) * 32;                                 \
    const __nv_bfloat16* _ap = (_r == 1) ? Alo : Asrc;                          \
    const __nv_bfloat16* _bp = (_r == 2) ? Blo : Bsrc;                          \
    _Pragma("unroll")                                                           \
    for (int _j = 0; _j < 2; _j++) {                                            \
        int _kc = kc0 + _j;                                                     \
        const void* _sa = _ap + _kb + _kc * 8;                                  \
        const void* _sb = _bp + _kb + _kc * 8;                                  \
        uint32_t _da = dA0 + (st) * 8192 + (((_kc) ^ swm) << 4);                \
        uint32_t _db = dB0 + (st) * 8192 + (((_kc) ^ swm) << 4);                \
        asm volatile("cp.async.cg.shared.global [%0], [%1], 16;" :: "r"(_da), "l"(_sa)); \
        asm volatile("cp.async.cg.shared.global [%0], [%1], 16;" :: "r"(_db), "l"(_sb)); \
    }                                                                           \
    asm volatile("cp.async.commit_group;");                                     \
} while (0)

    ISSUE(0, 0);
    ISSUE(1, 1);
    int cur = 0, nxt = 2;
    for (int ki = 0; ki < 48; ki++) {
        asm volatile("cp.async.wait_group 1;" ::: "memory");
        __syncthreads();
        if (ki + 2 < 48) ISSUE(ki + 2, nxt);
#pragma unroll
        for (int s = 0; s < 2; s++) {
            uint32_t a[4][4];
#pragma unroll
            for (int im = 0; im < 4; im++)
                ldsm4(a[im], aAddr[im] + cur * 8192 + (((kcbA + 2 * s) ^ aXor[im]) << 4));
            uint32_t bq[2][4];
#pragma unroll
            for (int p = 0; p < 2; p++)
                ldsm4(bq[p], bAddr[p] + cur * 8192 + (((kcbB + 2 * s) ^ bXor[p]) << 4));
#pragma unroll
            for (int im = 0; im < 4; im++)
#pragma unroll
                for (int in = 0; in < 4; in++)
                    mma16816(c[im][in], a[im], bq[in >> 1][(in & 1) * 2], bq[in >> 1][(in & 1) * 2 + 1]);
        }
        cur = (cur == 2) ? 0 : cur + 1;
        nxt = (nxt == 2) ? 0 : nxt + 1;
    }

    const float inv_scale = 0.044194173824159216f;  // 1/sqrt(512)
    int gid = lane >> 2, tig = lane & 3;
#pragma unroll
    for (int im = 0; im < 4; im++) {
#pragma unroll
        for (int hrow = 0; hrow < 2; hrow++) {
            int row = m0 + wm * 64 + im * 16 + gid + hrow * 8;
            int b = row >> 10, l = (row >> 6) & 15, nt = row & 63;
            int frl = (row >> 6) & 1;
#pragma unroll
            for (int in = 0; in < 4; in++) {
                int e = e0 + wn * 32 + in * 8 + 2 * tig;
                int h = (e >> 6) & 7, hd = e & 63;
                float v0 = c[im][in][2 * hrow + 0] + s_tq[frl * 64 + hd];
                float v1 = c[im][in][2 * hrow + 1] + s_tq[frl * 64 + hd + 1];
                size_t off = (size_t)((b * H_ + h) * NTOK_ + l * 64 + nt) * HD_ + hd;
                if (third == 0) {
                    *(float2*)(g_Q + off) = make_float2(v0 * inv_scale, v1 * inv_scale);
                } else {
                    __nv_bfloat16 h0 = __float2bfloat16_rn(v0), h1 = __float2bfloat16_rn(v1);
                    __nv_bfloat162 hv = __halves2bfloat162(h0, h1);
                    __nv_bfloat162 lv = __floats2bfloat162_rn(v0 - __bfloat162float(h0),
                                                              v1 - __bfloat162float(h1));
                    __nv_bfloat162* hiA = (third == 1) ? (__nv_bfloat162*)g_Khi : (__nv_bfloat162*)g_Vhi;
                    __nv_bfloat162* loA = (third == 1) ? (__nv_bfloat162*)g_Klo : (__nv_bfloat162*)g_Vlo;
                    hiA[off >> 1] = hv;
                    loA[off >> 1] = lv;
                }
            }
        }
    }
}

// ---------------------------------------------------------------------------
// Kernel 2: tensor-core fused attention.
// Changes vs round 6:
//  - Qs/Et fp32 staging ALIASED into the KV double-buffer region (only live
//    before the frame pipeline starts) -> ATT_SMEM 108KB -> ~84KB -> 2 CTAs/SM.
//  - Heavy-first scheduling: ql = 15 - blockIdx.x (causal blocks with most
//    frames launch first).
// smem layout (bytes):
//   [0, 65536)            KV[2][4][8192]  (stage, {Khi,Klo,Vhi,Vlo})
//       alias during init: Qs fp32 64x68 @0 (17408), Et 16x68 @17408 (4352)
//   [65536, 73728)        Qhi 64x64 bf16 swizzled
//   [73728, 81920)        Qlo
//   [81920, 86272)        bias 64x17 f32
//   [86272, 86340)        list[16] + nv
// ---------------------------------------------------------------------------
#define ATT_KV     0
#define ATT_QS     0
#define ATT_ET     17408
#define ATT_QHI    65536
#define ATT_QLO    (ATT_QHI + 8192)
#define ATT_BIAS   (ATT_QLO + 8192)
#define ATT_LIST   (ATT_BIAS + 64 * 17 * 4)
#define ATT_SMEM   (ATT_LIST + 68)

__global__ __launch_bounds__(128, 2) void attn_kernel(const int* __restrict__ pos,
                                                      const int* __restrict__ mask,
                                                      const float* __restrict__ emb,
                                                      float* __restrict__ out) {
    uint32_t sbase = smem_u32(smem_raw);
    float (*Qs)[68] = (float(*)[68])(smem_raw + ATT_QS);
    float (*Et)[68] = (float(*)[68])(smem_raw + ATT_ET);
    float (*bias)[17] = (float(*)[17])(smem_raw + ATT_BIAS);
    int* list = (int*)(smem_raw + ATT_LIST);

    int ql = (L_ - 1) - blockIdx.x;        // heavy-first
    int h = blockIdx.y, b = blockIdx.z;
    int tid = threadIdx.x;
    int lane = tid & 31, w = tid >> 5;
    int r0 = w * 16;
    int bh = b * H_ + h;

    // ---- valid-frame list
    if (tid == 0) {
        int nvl = 0;
        const int* mrow = mask + (b * L_ + ql) * L_;
#pragma unroll
        for (int kl = 0; kl < L_; kl++)
            if (mrow[kl] != 0) list[nvl++] = kl;
        list[16] = nvl;
    }

    // ---- load Q fp32, Et (into aliased KV region)
    const float* Qg = g_Q + ((size_t)bh * NTOK_ + ql * 64) * HD_;
    for (int i = tid; i < 1024; i += 128) {
        int r = i >> 4, c = (i & 15) << 2;
        *(float4*)&Qs[r][c] = *(const float4*)(Qg + r * HD_ + c);
    }
    for (int i = tid; i < 1024; i += 128) {
        int kl = i >> 6, c = i & 63;
        int p = pos[(b * L_ + ql) * L_ + kl];
        p = min(max(p, -8), 8) + 8;
        Et[kl][c] = emb[p * HD_ + c];
    }
    __syncthreads();
    int nv = list[16];

    // ---- bias[r][kl] = Qrow . Et[kl]
#pragma unroll
    for (int u = 0; u < 8; u++) {
        int id = tid + u * 128;
        int r = id >> 4, kl = id & 15;
        float acc = 0.f;
        const float* qrow = Qs[r];
        const float* erow = Et[kl];
#pragma unroll 16
        for (int c = 0; c < 64; c++) acc += qrow[c] * erow[c];
        bias[r][kl] = acc;
    }

    // ---- convert Q -> hi/lo bf16 swizzled tiles
#pragma unroll
    for (int i = 0; i < 4; i++) {
        int linear = i * 128 + tid;
        int row = linear >> 3, ch = linear & 7;
        const float* qp = &Qs[row][ch * 8];
        uint32_t hi4[4], lo4[4];
#pragma unroll
        for (int j = 0; j < 4; j++) {
            float x0 = qp[2 * j], x1 = qp[2 * j + 1];
            __nv_bfloat16 h0 = __float2bfloat16_rn(x0), h1 = __float2bfloat16_rn(x1);
            hi4[j] = packbf2(__bfloat162float(h0), __bfloat162float(h1));
            lo4[j] = packbf2(x0 - __bfloat162float(h0), x1 - __bfloat162float(h1));
        }
        uint32_t soff = row * 128 + ((ch ^ (row & 7)) << 4);
        *(uint4*)(smem_raw + ATT_QHI + soff) = *(uint4*)hi4;
        *(uint4*)(smem_raw + ATT_QLO + soff) = *(uint4*)lo4;
    }
    __syncthreads();   // Qs/Et dead after this point -> KV region free

    // ---- Q A-fragments (registers, once)
    uint32_t qh[4][4], qlr[4][4];
    {
        int lrow = (lane & 7) + 8 * ((lane >> 3) & 1);
        int khalf = lane >> 4;
#pragma unroll
        for (int kt = 0; kt < 4; kt++) {
            int qr = r0 + lrow;
            int qc = kt * 2 + khalf;
            uint32_t off = qr * 128 + ((qc ^ (qr & 7)) << 4);
            ldsm4(qh[kt],  sbase + ATT_QHI + off);
            ldsm4(qlr[kt], sbase + ATT_QLO + off);
        }
    }

    int g4 = lane >> 2;
    float m0r = -INFINITY, m1r = -INFINITY, l0r = 0.f, l1r = 0.f;
    float O[8][4] = {};

    int klrow = (lane & 7) + 8 * (lane >> 4);
    int kchalf = (lane >> 3) & 1;
    int vlrow = (lane & 7) + 8 * ((lane >> 3) & 1);
    int vchalf = lane >> 4;

    const __nv_bfloat16* tile_src[4] = {
        g_Khi + (size_t)bh * NTOK_ * HD_, g_Klo + (size_t)bh * NTOK_ * HD_,
        g_Vhi + (size_t)bh * NTOK_ * HD_, g_Vlo + (size_t)bh * NTOK_ * HD_
    };
    const __nv_bfloat16* mysrc = tile_src[w];
    uint32_t mydst = sbase + ATT_KV + w * 8192;

#define ISSUE_FRAME(f, stage) do {                                              \
    const __nv_bfloat16* _s = mysrc + (f) * 4096;                               \
    uint32_t _d = mydst + (stage) * 32768;                                      \
    _Pragma("unroll")                                                           \
    for (int _c = 0; _c < 16; _c++) {                                           \
        int _lin = _c * 32 + lane;                                              \
        int _row = _lin >> 3, _ch = _lin & 7;                                   \
        uint32_t _da = _d + _row * 128 + ((_ch ^ (_row & 7)) << 4);             \
        asm volatile("cp.async.cg.shared.global [%0], [%1], 16;"                \
                     :: "r"(_da), "l"(_s + _row * 64 + _ch * 8));               \
    }                                                                           \
    asm volatile("cp.async.commit_group;");                                     \
} while (0)

    ISSUE_FRAME(list[0], 0);

    for (int j = 0; j < nv; j++) {
        int stage = j & 1;
        if (j + 1 < nv) {
            ISSUE_FRAME(list[j + 1], (j + 1) & 1);
            asm volatile("cp.async.wait_group 1;" ::: "memory");
        } else {
            asm volatile("cp.async.wait_group 0;" ::: "memory");
        }
        __syncthreads();
        int kl = list[j];
        uint32_t khiB = sbase + ATT_KV + stage * 32768;
        uint32_t kloB = khiB + 8192;
        uint32_t vhiB = khiB + 16384;
        uint32_t vloB = khiB + 24576;

        // ---- S = bias + Q.K^T (3-term split)
        float S[8][4];
        float bb0 = bias[r0 + g4][kl], bb1 = bias[r0 + 8 + g4][kl];
#pragma unroll
        for (int nt = 0; nt < 8; nt++) {
            S[nt][0] = bb0; S[nt][1] = bb0; S[nt][2] = bb1; S[nt][3] = bb1;
        }
#pragma unroll
        for (int kt = 0; kt < 4; kt++) {
#pragma unroll
            for (int np = 0; np < 4; np++) {
                int nr = np * 16 + klrow;
                int kc = kt * 2 + kchalf;
                uint32_t off = nr * 128 + ((kc ^ (nr & 7)) << 4);
                uint32_t kh[4], klo2[4];
                ldsm4(kh,   khiB + off);
                ldsm4(klo2, kloB + off);
                mma16816(S[2 * np],     qh[kt],  kh[0],   kh[1]);
                mma16816(S[2 * np + 1], qh[kt],  kh[2],   kh[3]);
                mma16816(S[2 * np],     qlr[kt], kh[0],   kh[1]);
                mma16816(S[2 * np + 1], qlr[kt], kh[2],   kh[3]);
                mma16816(S[2 * np],     qh[kt],  klo2[0], klo2[1]);
                mma16816(S[2 * np + 1], qh[kt],  klo2[2], klo2[3]);
            }
        }

        // ---- online softmax
        float mx0 = -INFINITY, mx1 = -INFINITY;
#pragma unroll
        for (int nt = 0; nt < 8; nt++) {
            mx0 = fmaxf(mx0, fmaxf(S[nt][0], S[nt][1]));
            mx1 = fmaxf(mx1, fmaxf(S[nt][2], S[nt][3]));
        }
        mx0 = fmaxf(mx0, __shfl_xor_sync(0xffffffffu, mx0, 1));
        mx0 = fmaxf(mx0, __shfl_xor_sync(0xffffffffu, mx0, 2));
        mx1 = fmaxf(mx1, __shfl_xor_sync(0xffffffffu, mx1, 1));
        mx1 = fmaxf(mx1, __shfl_xor_sync(0xffffffffu, mx1, 2));
        float mn0 = fmaxf(m0r, mx0), mn1 = fmaxf(m1r, mx1);
        float corr0 = __expf(m0r - mn0), corr1 = __expf(m1r - mn1);
        float sum0 = 0.f, sum1 = 0.f;
#pragma unroll
        for (int nt = 0; nt < 8; nt++) {
            S[nt][0] = __expf(S[nt][0] - mn0); S[nt][1] = __expf(S[nt][1] - mn0);
            S[nt][2] = __expf(S[nt][2] - mn1); S[nt][3] = __expf(S[nt][3] - mn1);
            sum0 += S[nt][0] + S[nt][1];
            sum1 += S[nt][2] + S[nt][3];
        }
        sum0 += __shfl_xor_sync(0xffffffffu, sum0, 1);
        sum0 += __shfl_xor_sync(0xffffffffu, sum0, 2);
        sum1 += __shfl_xor_sync(0xffffffffu, sum1, 1);
        sum1 += __shfl_xor_sync(0xffffffffu, sum1, 2);
        l0r = l0r * corr0 + sum0; m0r = mn0;
        l1r = l1r * corr1 + sum1; m1r = mn1;

        // ---- P hi/lo A-fragments
        uint32_t ph[4][4], pl[4][4];
#pragma unroll
        for (int kt = 0; kt < 4; kt++) {
#pragma unroll
            for (int q = 0; q < 4; q++) {
                int nt = 2 * kt + (q >> 1);
                float x0 = S[nt][(q & 1) * 2], x1 = S[nt][(q & 1) * 2 + 1];
                __nv_bfloat16 hx0 = __float2bfloat16_rn(x0), hx1 = __float2bfloat16_rn(x1);
                __nv_bfloat162 hp2 = __halves2bfloat162(hx0, hx1);
                ph[kt][q] = *(uint32_t*)&hp2;
                __nv_bfloat162 lp2 = __floats2bfloat162_rn(x0 - __bfloat162float(hx0),
                                                           x1 - __bfloat162float(hx1));
                pl[kt][q] = *(uint32_t*)&lp2;
            }
        }

        // ---- O = O*corr + P.V (3-term split)
#pragma unroll
        for (int nt = 0; nt < 8; nt++) {
            O[nt][0] *= corr0; O[nt][1] *= corr0; O[nt][2] *= corr1; O[nt][3] *= corr1;
        }
#pragma unroll
        for (int kt = 0; kt < 4; kt++) {
#pragma unroll
            for (int np = 0; np < 4; np++) {
                int vr = kt * 16 + vlrow;
                int vc = np * 2 + vchalf;
                uint32_t off = vr * 128 + ((vc ^ (vr & 7)) << 4);
                uint32_t vh[4], vl[4];
                ldsm4t(vh, vhiB + off);
                ldsm4t(vl, vloB + off);
                mma16816(O[2 * np],     ph[kt], vh[0], vh[1]);
                mma16816(O[2 * np + 1], ph[kt], vh[2], vh[3]);
                mma16816(O[2 * np],     pl[kt], vh[0], vh[1]);
                mma16816(O[2 * np + 1], pl[kt], vh[2], vh[3]);
                mma16816(O[2 * np],     ph[kt], vl[0], vl[1]);
                mma16816(O[2 * np + 1], ph[kt], vl[2], vl[3]);
            }
        }
        __syncthreads();
    }

    // ---- finalize, store
    float inv0 = 1.f / l0r, inv1 = 1.f / l1r;
    int ra = ql * 64 + r0 + g4;
    int colb = h * HD_ + 2 * (lane & 3);
    float* ob = out + (size_t)((b * L_) * 64 + ra) * D_ + colb;
#pragma unroll
    for (int nt = 0; nt < 8; nt++) {
        *(float2*)(ob + nt * 8)          = make_float2(O[nt][0] * inv0, O[nt][1] * inv0);
        *(float2*)(ob + 8 * D_ + nt * 8) = make_float2(O[nt][2] * inv1, O[nt][3] * inv1);
    }
}

// ---------------------------------------------------------------------------
extern "C" void kernel_launch(void* const* d_in, const int* in_sizes, int n_in,
                              void* d_out, int out_size) {
    const float* x    = (const float*)d_in[0];
    const float* te   = (const float*)d_in[1];
    const int*   pos  = (const int*)d_in[2];
    const int*   mask = (const int*)d_in[3];
    const float* Wqkv = (const float*)d_in[4];
    const float* Wt   = (const float*)d_in[5];
    const float* emb  = (const float*)d_in[6];
    float* out = (float*)d_out;

    cudaFuncSetAttribute(qkv_gemm, cudaFuncAttributeMaxDynamicSharedMemorySize, GEMM_SMEM);
    cudaFuncSetAttribute(attn_kernel, cudaFuncAttributeMaxDynamicSharedMemorySize, ATT_SMEM);

    split_kernel<<<(XQUADS + WQUADS) / 256, 256>>>(x, Wqkv);
    qkv_gemm<<<dim3(E3_ / 128, 4096 / 128), 256, GEMM_SMEM>>>(te, Wt);
    attn_kernel<<<dim3(L_, H_, B_), 128, ATT_SMEM>>>(pos, mask, emb, out);
}